// round 10
// baseline (speedup 1.0000x reference)
#include <cuda_runtime.h>
#include <cstdint>
#include <cstddef>

// ---------------------------------------------------------------------------
// TinyTransformer B=4 S=2048 D=512 V=32000 — legacy tf32 mma.sync.
// R9: operands stored k-PERMUTED (w(k)=(k&3)*8+(k&4)+(k&31)/8 within each
// 32-block) so fragment loads become LDS.128 (4x fewer shared loads).
// Producers write permuted; cp.async staging stays 16B-contiguous.
// qkv/scores/logits use the permuted path; attnv keeps the legacy path.
// ---------------------------------------------------------------------------

#define BATCH 4
#define SEQ   2048
#define DIM   512
#define VOCAB 32000
#define NQKV  1536
#define MTOK  8192

#define BM 128
#define BN 128
#define BK 32
#define AST 36     // permuted-row stride (36 % 32 == 4 -> conflict-free LDS.128)
#define BST 136    // legacy k-major B stride (attnv)

__device__ float g_qkv[(size_t)MTOK * NQKV];      // Q,K sections k-permuted; V normal
__device__ float g_scores[(size_t)BATCH * SEQ * SEQ];
__device__ float g_attn_out[(size_t)MTOK * DIM];  // k-permuted
__device__ float g_embed_r[(size_t)VOCAB * DIM];  // rounded + k-permuted
__device__ float g_qkvwT[(size_t)NQKV * DIM];     // rounded + transposed + k-permuted
__device__ float g_fcwT[(size_t)VOCAB * DIM];     // rounded + transposed + k-permuted

__device__ __forceinline__ uint32_t f2tf(float f) {
    uint32_t u;
    asm("cvt.rna.tf32.f32 %0, %1;" : "=r"(u) : "f"(f));
    return u;
}
__device__ __forceinline__ float rnd(float f) { return __uint_as_float(f2tf(f)); }
__device__ __forceinline__ int wperm32(int k) {      // bijection on [0,32)
    return ((k & 3) << 3) | (k & 4) | ((k & 31) >> 3);
}

__device__ __forceinline__ void cpa16(void* s, const float* g) {
    uint32_t sa = (uint32_t)__cvta_generic_to_shared(s);
    asm volatile("cp.async.cg.shared.global [%0], [%1], 16;" :: "r"(sa), "l"(g));
}
#define CP_COMMIT() asm volatile("cp.async.commit_group;")
#define CP_WAIT0()  asm volatile("cp.async.wait_group 0;")

#define MMA_TF32(c, a, b0, b1)                                                 \
    asm volatile(                                                              \
        "mma.sync.aligned.m16n8k8.row.col.f32.tf32.tf32.f32 "                  \
        "{%0,%1,%2,%3},{%4,%5,%6,%7},{%8,%9},{%0,%1,%2,%3};"                   \
        : "+f"(c[0]), "+f"(c[1]), "+f"(c[2]), "+f"(c[3])                       \
        : "r"(a[0]), "r"(a[1]), "r"(a[2]), "r"(a[3]), "r"(b0), "r"(b1));

#define ACC_INIT()                                                             \
    float acc[2][8][4];                                                        \
    _Pragma("unroll")                                                          \
    for (int i = 0; i < 2; i++)                                                \
        _Pragma("unroll")                                                      \
        for (int j = 0; j < 8; j++)                                            \
            _Pragma("unroll")                                                  \
            for (int k = 0; k < 4; k++) acc[i][j][k] = 0.f;

// Permuted-layout compute: one 32-k block. As:[m][STA] Bs:[n][STB], both
// k-permuted rows. All fragment loads are LDS.128.
#define TILE_COMPUTE_P(As, Bs, STA, STB, OFF)                                  \
    {                                                                          \
        uint32_t a0[2][4], a1[2][4], a2[2][4], a3[2][4];                       \
        _Pragma("unroll")                                                      \
        for (int mi = 0; mi < 2; mi++) {                                       \
            int mr = wm + mi * 16 + g;                                         \
            *(uint4*)a0[mi] = *(const uint4*)((As) + mr * STA + (OFF) + t * 8);      \
            *(uint4*)a2[mi] = *(const uint4*)((As) + mr * STA + (OFF) + t * 8 + 4);  \
            *(uint4*)a1[mi] = *(const uint4*)((As) + (mr + 8) * STA + (OFF) + t * 8);\
            *(uint4*)a3[mi] = *(const uint4*)((As) + (mr + 8) * STA + (OFF) + t * 8 + 4);\
        }                                                                      \
        _Pragma("unroll")                                                      \
        for (int ni = 0; ni < 8; ni++) {                                       \
            int nr = wn + ni * 8 + g;                                          \
            uint32_t bl[4], bh[4];                                             \
            *(uint4*)bl = *(const uint4*)((Bs) + nr * STB + (OFF) + t * 8);    \
            *(uint4*)bh = *(const uint4*)((Bs) + nr * STB + (OFF) + t * 8 + 4);\
            _Pragma("unroll")                                                  \
            for (int kb = 0; kb < 4; kb++) {                                   \
                uint32_t af0[4] = {a0[0][kb], a1[0][kb], a2[0][kb], a3[0][kb]};\
                uint32_t af1[4] = {a0[1][kb], a1[1][kb], a2[1][kb], a3[1][kb]};\
                MMA_TF32(acc[0][ni], af0, bl[kb], bh[kb]);                     \
                MMA_TF32(acc[1][ni], af1, bl[kb], bh[kb]);                     \
            }                                                                  \
        }                                                                      \
    }

// Legacy compute (attnv): As m-major [128][AST], Bs k-major [32][BST].
#define TILE_COMPUTE_KN(As, Bs)                                                \
    _Pragma("unroll")                                                          \
    for (int kk = 0; kk < 4; kk++) {                                           \
        uint32_t bf[8][2];                                                     \
        _Pragma("unroll")                                                      \
        for (int ni = 0; ni < 8; ni++) {                                       \
            bf[ni][0] = (Bs)[(kk * 8 + t) * BST + wn + ni * 8 + g];            \
            bf[ni][1] = (Bs)[(kk * 8 + t + 4) * BST + wn + ni * 8 + g];        \
        }                                                                      \
        uint32_t af[2][4];                                                     \
        _Pragma("unroll")                                                      \
        for (int mi = 0; mi < 2; mi++) {                                       \
            int mr = wm + mi * 16 + g;                                         \
            af[mi][0] = (As)[mr * AST + kk * 8 + t];                           \
            af[mi][1] = (As)[(mr + 8) * AST + kk * 8 + t];                     \
            af[mi][2] = (As)[mr * AST + kk * 8 + t + 4];                       \
            af[mi][3] = (As)[(mr + 8) * AST + kk * 8 + t + 4];                 \
        }                                                                      \
        _Pragma("unroll")                                                      \
        for (int ni = 0; ni < 8; ni++) {                                       \
            MMA_TF32(acc[0][ni], af[0], bf[ni][0], bf[ni][1]);                 \
            MMA_TF32(acc[1][ni], af[1], bf[ni][0], bf[ni][1]);                 \
        }                                                                      \
    }

// Stage 128 rows x 32 words into [r][AST] (permuted sources are contiguous).
#define STAGE_P_ASY(DST, PTR_EXPR)                                             \
    _Pragma("unroll")                                                          \
    for (int i = 0; i < 4; i++) {                                              \
        int v = tid + i * 256, r = v >> 3, kv = (v & 7) * 4;                   \
        cpa16((DST) + r * AST + kv, PTR_EXPR);                                 \
    }
#define STAGE_B_ASY(DST, PTR_EXPR)                                             \
    _Pragma("unroll")                                                          \
    for (int i = 0; i < 4; i++) {                                              \
        int v = tid + i * 256, r = v >> 5, nv = (v & 31) * 4;                  \
        cpa16((DST) + r * BST + nv, PTR_EXPR);                                 \
    }

// ---------------------------------------------------------------------------
// 0a) embed: round + k-permute rows  (dst[r][wperm(d)] = rnd(src[r][d]))
// ---------------------------------------------------------------------------
__global__ __launch_bounds__(256)
void round_permute_kernel(const float* __restrict__ src, float* __restrict__ dst)
{
    int i = blockIdx.x * 256 + threadIdx.x;           // one element each
    int r = i >> 9, d = i & 511;
    int wd = (d & ~31) | wperm32(d);
    dst[(size_t)r * DIM + wd] = rnd(src[i]);
}

// ---------------------------------------------------------------------------
// 0b) weights: round + transpose + k-permute  src[k][n] -> dst[n][wperm(k)]
// ---------------------------------------------------------------------------
__global__ __launch_bounds__(256)
void transpose_permute_kernel(const float* __restrict__ src,
                              float* __restrict__ dst, int ncols)
{
    __shared__ float tile[32][33];
    const int c0 = blockIdx.x * 32;      // n tile
    const int r0 = blockIdx.y * 32;      // k tile
    const int xx = threadIdx.x & 31, yy = threadIdx.x >> 5;
    #pragma unroll
    for (int i = 0; i < 32; i += 8)
        tile[yy + i][xx] = src[(size_t)(r0 + yy + i) * ncols + c0 + xx];
    __syncthreads();
    const int wx = wperm32(xx);
    #pragma unroll
    for (int i = 0; i < 32; i += 8)
        dst[(size_t)(c0 + yy + i) * DIM + r0 + wx] = rnd(tile[xx][yy + i]);
}

// ---------------------------------------------------------------------------
// 1) qkv = gather(embed, x) @ qkv_w + b   (permuted path; Q/K stored permuted)
// ---------------------------------------------------------------------------
__global__ __launch_bounds__(256, 2)
void qkv_kernel(const int* __restrict__ x, const float* __restrict__ bias)
{
    extern __shared__ uint32_t sm[];
    int*      rows = (int*)sm;                 // 128
    uint32_t* Ab   = sm + 128;                 // 2 * 128*AST
    uint32_t* Bb   = Ab + 2 * BM * AST;        // 2 * 128*AST (n-major permuted)
    const int tid = threadIdx.x;
    const int lane = tid & 31, wid = tid >> 5;
    const int wm = (wid & 3) * 32, wn = (wid >> 2) * 64;
    const int g = lane >> 2, t = lane & 3;
    ACC_INIT();
    const int m0 = blockIdx.y * BM;
    const int n0 = blockIdx.x * BN;
    if (tid < BM) rows[tid] = x[m0 + tid];
    __syncthreads();

    STAGE_P_ASY(Ab, g_embed_r + (size_t)rows[r] * DIM + kv);
    STAGE_P_ASY(Bb, g_qkvwT + (size_t)(n0 + r) * DIM + kv);
    CP_COMMIT();
    for (int c = 0; c < 16; c++) {
        const int bf_ = c & 1;
        CP_WAIT0();
        __syncthreads();
        if (c + 1 < 16) {
            const int k1 = (c + 1) * BK;
            uint32_t* An = Ab + (bf_ ^ 1) * BM * AST;
            uint32_t* Bn = Bb + (bf_ ^ 1) * BM * AST;
            STAGE_P_ASY(An, g_embed_r + (size_t)rows[r] * DIM + k1 + kv);
            STAGE_P_ASY(Bn, g_qkvwT + (size_t)(n0 + r) * DIM + k1 + kv);
            CP_COMMIT();
        }
        TILE_COMPUTE_P(Ab + bf_ * BM * AST, Bb + bf_ * BM * AST, AST, AST, 0);
    }
    #pragma unroll
    for (int mi = 0; mi < 2; mi++)
        #pragma unroll
        for (int ni = 0; ni < 8; ni++) {
            int r0 = m0 + wm + mi * 16 + g;
            int c  = n0 + wn + ni * 8 + t * 2;
            float b0 = bias[c], b1 = bias[c + 1];
            float v0 = rnd(acc[mi][ni][0] + b0), v1 = rnd(acc[mi][ni][1] + b1);
            float v2 = rnd(acc[mi][ni][2] + b0), v3 = rnd(acc[mi][ni][3] + b1);
            if (c < 1024) {        // Q/K: store k-permuted (uniform per CTA)
                int w0 = (c & ~31) | wperm32(c);
                int w1 = ((c + 1) & ~31) | wperm32(c + 1);
                g_qkv[(size_t)r0 * NQKV + w0] = v0;
                g_qkv[(size_t)r0 * NQKV + w1] = v1;
                g_qkv[(size_t)(r0 + 8) * NQKV + w0] = v2;
                g_qkv[(size_t)(r0 + 8) * NQKV + w1] = v3;
            } else {               // V: normal layout (attnv legacy path)
                *(float2*)(g_qkv + (size_t)r0 * NQKV + c) = make_float2(v0, v1);
                *(float2*)(g_qkv + (size_t)(r0 + 8) * NQKV + c) = make_float2(v2, v3);
            }
        }
}

// ---------------------------------------------------------------------------
// 2) scores = Q @ K^T * scale   (both operands permuted-row layout)
// ---------------------------------------------------------------------------
__global__ __launch_bounds__(256, 2)
void scores_kernel()
{
    if (blockIdx.x > blockIdx.y) return;
    extern __shared__ uint32_t sm[];
    uint32_t* Ab = sm;
    uint32_t* Bb = Ab + 2 * BM * AST;
    const int tid = threadIdx.x;
    const int lane = tid & 31, wid = tid >> 5;
    const int wm = (wid & 3) * 32, wn = (wid >> 2) * 64;
    const int g = lane >> 2, t = lane & 3;
    ACC_INIT();
    const int b  = blockIdx.z;
    const int q0 = blockIdx.y * BM;
    const int n0 = blockIdx.x * BN;
    const float* Q = g_qkv + (size_t)(b * SEQ) * NQKV;
    const float* K = Q + DIM;

    STAGE_P_ASY(Ab, Q + (size_t)(q0 + r) * NQKV + kv);
    STAGE_P_ASY(Bb, K + (size_t)(n0 + r) * NQKV + kv);
    CP_COMMIT();
    for (int c = 0; c < 16; c++) {
        const int bf_ = c & 1;
        CP_WAIT0();
        __syncthreads();
        if (c + 1 < 16) {
            const int k1 = (c + 1) * BK;
            uint32_t* An = Ab + (bf_ ^ 1) * BM * AST;
            uint32_t* Bn = Bb + (bf_ ^ 1) * BM * AST;
            STAGE_P_ASY(An, Q + (size_t)(q0 + r) * NQKV + k1 + kv);
            STAGE_P_ASY(Bn, K + (size_t)(n0 + r) * NQKV + k1 + kv);
            CP_COMMIT();
        }
        TILE_COMPUTE_P(Ab + bf_ * BM * AST, Bb + bf_ * BM * AST, AST, AST, 0);
    }
    const float scale = 0.044194173824159216f;
    #pragma unroll
    for (int mi = 0; mi < 2; mi++)
        #pragma unroll
        for (int ni = 0; ni < 8; ni++) {
            int r0 = q0 + wm + mi * 16 + g;
            int c  = n0 + wn + ni * 8 + t * 2;
            float* p0 = g_scores + (size_t)(b * SEQ + r0) * SEQ + c;
            float* p1 = p0 + (size_t)8 * SEQ;
            *(float2*)p0 = make_float2(acc[mi][ni][0] * scale, acc[mi][ni][1] * scale);
            *(float2*)p1 = make_float2(acc[mi][ni][2] * scale, acc[mi][ni][3] * scale);
        }
}

// ---------------------------------------------------------------------------
// 3) causal softmax, smem-resident; zero only intra-tile masked strip
// ---------------------------------------------------------------------------
__global__ __launch_bounds__(256)
void softmax_kernel()
{
    const int row = blockIdx.x;
    const int q = row & (SEQ - 1);
    float* p = g_scores + (size_t)row * SEQ;
    const int L = q + 1;
    const int kend = (q & ~127) + 128;
    const int tid = threadIdx.x;
    const int lane = tid & 31, wid = tid >> 5;
    __shared__ float red[8];
    __shared__ float ebuf[SEQ];

    float m = -1e30f;
    for (int k = tid; k < L; k += 256) {
        float v = p[k];
        ebuf[k] = v;
        m = fmaxf(m, v);
    }
    #pragma unroll
    for (int s = 16; s > 0; s >>= 1) m = fmaxf(m, __shfl_xor_sync(~0u, m, s));
    if (lane == 0) red[wid] = m;
    __syncthreads();
    m = red[lane & 7];
    #pragma unroll
    for (int s = 4; s > 0; s >>= 1) m = fmaxf(m, __shfl_xor_sync(~0u, m, s));

    float sum = 0.f;
    for (int k = tid; k < L; k += 256) {
        float e = __expf(ebuf[k] - m);
        ebuf[k] = e;
        sum += e;
    }
    #pragma unroll
    for (int s = 16; s > 0; s >>= 1) sum += __shfl_xor_sync(~0u, sum, s);
    __syncthreads();
    if (lane == 0) red[wid] = sum;
    __syncthreads();
    sum = red[lane & 7];
    #pragma unroll
    for (int s = 4; s > 0; s >>= 1) sum += __shfl_xor_sync(~0u, sum, s);

    const float inv = 1.0f / sum;
    for (int k = tid; k < L; k += 256) p[k] = rnd(ebuf[k] * inv);
    for (int k = L + tid; k < kend; k += 256) p[k] = 0.f;
}

// ---------------------------------------------------------------------------
// 4) out = attn @ V  (legacy path; output stored k-PERMUTED for logits)
// ---------------------------------------------------------------------------
__global__ __launch_bounds__(256, 2)
void attnv_kernel()
{
    extern __shared__ uint32_t sm[];
    uint32_t* Ab = sm;
    uint32_t* Bb = Ab + 2 * BM * AST;
    const int tid = threadIdx.x;
    const int lane = tid & 31, wid = tid >> 5;
    const int wm = (wid & 3) * 32, wn = (wid >> 2) * 64;
    const int g = lane >> 2, t = lane & 3;
    ACC_INIT();
    const int b  = blockIdx.z;
    const int q0 = blockIdx.y * BM;
    const int n0 = blockIdx.x * BN;
    const float* A  = g_scores + (size_t)(b * SEQ) * SEQ;
    const float* Vm = g_qkv + (size_t)(b * SEQ) * NQKV + 2 * DIM;

    #pragma unroll
    for (int i = 0; i < 4; i++) {
        int v = tid + i * 256, r = v >> 3, kv = (v & 7) * 4;
        cpa16(Ab + r * AST + kv, A + (size_t)(q0 + r) * SEQ + kv);
    }
    STAGE_B_ASY(Bb, Vm + (size_t)r * NQKV + n0 + nv);
    CP_COMMIT();

    const int NC = (q0 + BM) / BK;
    for (int c = 0; c < NC; c++) {
        const int bf_ = c & 1;
        CP_WAIT0();
        __syncthreads();
        if (c + 1 < NC) {
            const int k1 = (c + 1) * BK;
            uint32_t* An = Ab + (bf_ ^ 1) * BM * AST;
            uint32_t* Bn = Bb + (bf_ ^ 1) * BK * BST;
            #pragma unroll
            for (int i = 0; i < 4; i++) {
                int v = tid + i * 256, r = v >> 3, kv = (v & 7) * 4;
                cpa16(An + r * AST + kv, A + (size_t)(q0 + r) * SEQ + k1 + kv);
            }
            STAGE_B_ASY(Bn, Vm + (size_t)(k1 + r) * NQKV + n0 + nv);
            CP_COMMIT();
        }
        TILE_COMPUTE_KN(Ab + bf_ * BM * AST, Bb + bf_ * BK * BST);
    }
    #pragma unroll
    for (int mi = 0; mi < 2; mi++)
        #pragma unroll
        for (int ni = 0; ni < 8; ni++) {
            int r0 = q0 + wm + mi * 16 + g;
            int c  = n0 + wn + ni * 8 + t * 2;
            int w0 = (c & ~31) | wperm32(c);
            int w1 = ((c + 1) & ~31) | wperm32(c + 1);
            float* base0 = g_attn_out + (size_t)(b * SEQ + r0) * DIM;
            float* base1 = base0 + (size_t)8 * DIM;
            base0[w0] = rnd(acc[mi][ni][0]);
            base0[w1] = rnd(acc[mi][ni][1]);
            base1[w0] = rnd(acc[mi][ni][2]);
            base1[w1] = rnd(acc[mi][ni][3]);
        }
}

// ---------------------------------------------------------------------------
// 5) logits = attn_out @ fc_w^T + b   (permuted path, 256x128, BK=64)
// ---------------------------------------------------------------------------
#define LBM  256
#define LBK  64
#define LST  68    // 68 % 32 == 4 -> conflict-free LDS.128

__global__ __launch_bounds__(512, 1)
void logits_kernel(const float* __restrict__ bias, float* __restrict__ out)
{
    extern __shared__ uint32_t sm[];
    uint32_t* Ab = sm;                        // 2 * 256*LST
    uint32_t* Bb = Ab + 2 * LBM * LST;        // 2 * 128*LST
    const int tid = threadIdx.x;
    const int lane = tid & 31, wid = tid >> 5;
    const int wm = (wid & 7) * 32, wn = (wid >> 3) * 64;
    const int g = lane >> 2, t = lane & 3;
    ACC_INIT();
    const int m0 = blockIdx.y * LBM;
    const int n0 = blockIdx.x * BN;

    #pragma unroll
    for (int i = 0; i < 8; i++) {
        int v = tid + i * 512, r = v >> 4, kv = (v & 15) * 4;
        cpa16(Ab + r * LST + kv, g_attn_out + (size_t)(m0 + r) * DIM + kv);
    }
    #pragma unroll
    for (int i = 0; i < 4; i++) {
        int v = tid + i * 512, r = v >> 4, kv = (v & 15) * 4;
        cpa16(Bb + r * LST + kv, g_fcwT + (size_t)(n0 + r) * DIM + kv);
    }
    CP_COMMIT();

    for (int c = 0; c < 8; c++) {
        const int bf_ = c & 1;
        CP_WAIT0();
        __syncthreads();
        if (c + 1 < 8) {
            const int k1 = (c + 1) * LBK;
            uint32_t* An = Ab + (bf_ ^ 1) * LBM * LST;
            uint32_t* Bn = Bb + (bf_ ^ 1) * BM * LST;
            #pragma unroll
            for (int i = 0; i < 8; i++) {
                int v = tid + i * 512, r = v >> 4, kv = (v & 15) * 4;
                cpa16(An + r * LST + kv,
                      g_attn_out + (size_t)(m0 + r) * DIM + k1 + kv);
            }
            #pragma unroll
            for (int i = 0; i < 4; i++) {
                int v = tid + i * 512, r = v >> 4, kv = (v & 15) * 4;
                cpa16(Bn + r * LST + kv,
                      g_fcwT + (size_t)(n0 + r) * DIM + k1 + kv);
            }
            CP_COMMIT();
        }
        const uint32_t* As = Ab + bf_ * LBM * LST;
        const uint32_t* Bs = Bb + bf_ * BM * LST;
        TILE_COMPUTE_P(As, Bs, LST, LST, 0);
        TILE_COMPUTE_P(As, Bs, LST, LST, 32);
    }
    #pragma unroll
    for (int mi = 0; mi < 2; mi++)
        #pragma unroll
        for (int ni = 0; ni < 8; ni++) {
            int r0 = m0 + wm + mi * 16 + g;
            int c  = n0 + wn + ni * 8 + t * 2;
            float b0 = bias[c], b1 = bias[c + 1];
            float* p0 = out + (size_t)r0 * VOCAB + c;
            float* p1 = out + (size_t)(r0 + 8) * VOCAB + c;
            *(float2*)p0 = make_float2(acc[mi][ni][0] + b0, acc[mi][ni][1] + b1);
            *(float2*)p1 = make_float2(acc[mi][ni][2] + b0, acc[mi][ni][3] + b1);
        }
}

// ---------------------------------------------------------------------------
extern "C" void kernel_launch(void* const* d_in, const int* in_sizes, int n_in,
                              void* d_out, int out_size)
{
    (void)in_sizes; (void)n_in; (void)out_size;
    const int*   x     = (const int*)  d_in[0];
    const float* embed = (const float*)d_in[1];
    const float* qkv_w = (const float*)d_in[2];
    const float* qkv_b = (const float*)d_in[3];
    const float* fc_w  = (const float*)d_in[4];
    const float* fc_b  = (const float*)d_in[5];
    float* out = (float*)d_out;

    const int smem_qkv    = (128 + 4 * BM * AST) * 4;             // ~74 KB
    const int smem_scores = (4 * BM * AST) * 4;                   // ~74 KB
    const int smem_attnv  = (2 * BM * AST + 2 * BK * BST) * 4;    // ~72 KB
    const int smem_logits = (2 * LBM * LST + 2 * BM * LST) * 4;   // ~209 KB

    cudaFuncSetAttribute(qkv_kernel,
        cudaFuncAttributeMaxDynamicSharedMemorySize, smem_qkv);
    cudaFuncSetAttribute(scores_kernel,
        cudaFuncAttributeMaxDynamicSharedMemorySize, smem_scores);
    cudaFuncSetAttribute(attnv_kernel,
        cudaFuncAttributeMaxDynamicSharedMemorySize, smem_attnv);
    cudaFuncSetAttribute(logits_kernel,
        cudaFuncAttributeMaxDynamicSharedMemorySize, smem_logits);

    float* emb_dst;  cudaGetSymbolAddress((void**)&emb_dst,  g_embed_r);
    float* qkvw_dst; cudaGetSymbolAddress((void**)&qkvw_dst, g_qkvwT);
    float* fcw_dst;  cudaGetSymbolAddress((void**)&fcw_dst,  g_fcwT);

    round_permute_kernel<<<VOCAB * DIM / 256, 256>>>(embed, emb_dst);
    transpose_permute_kernel<<<dim3(NQKV / 32, DIM / 32), 256>>>(qkv_w, qkvw_dst, NQKV);
    transpose_permute_kernel<<<dim3(VOCAB / 32, DIM / 32), 256>>>(fc_w, fcw_dst, VOCAB);

    qkv_kernel    <<<dim3(NQKV / BN, MTOK / BM), 256, smem_qkv>>>(x, qkv_b);
    scores_kernel <<<dim3(SEQ / BN, SEQ / BM, BATCH), 256, smem_scores>>>();
    softmax_kernel<<<MTOK, 256>>>();
    attnv_kernel  <<<dim3(DIM / BN, SEQ / BM, BATCH), 256, smem_attnv>>>();
    logits_kernel <<<dim3(VOCAB / BN, MTOK / LBM), 512, smem_logits>>>(fc_b, out);
}

// round 11
// speedup vs baseline: 1.3579x; 1.3579x over previous
#include <cuda_runtime.h>
#include <cstdint>
#include <cstddef>

// ---------------------------------------------------------------------------
// TinyTransformer B=4 S=2048 D=512 V=32000 — legacy tf32 mma.sync.
// R10 = R7 GEMM core (best known: 2 CTA/SM, 128 regs, wait0 double-buffer)
//     + smem-resident softmax with minimal tail zeroing.
// ---------------------------------------------------------------------------

#define BATCH 4
#define SEQ   2048
#define DIM   512
#define VOCAB 32000
#define NQKV  1536
#define MTOK  8192

#define BM 128
#define BN 128
#define BK 32
#define AST 36     // bank(4g+t) bijective
#define BST 136    // bank(8t+g) bijective

__device__ float g_qkv[(size_t)MTOK * NQKV];
__device__ float g_scores[(size_t)BATCH * SEQ * SEQ];
__device__ float g_attn_out[(size_t)MTOK * DIM];
__device__ float g_embed_r[(size_t)VOCAB * DIM];
__device__ float g_qkvw_r[(size_t)DIM * NQKV];
__device__ float g_fcw_r[(size_t)DIM * VOCAB];

__device__ __forceinline__ uint32_t f2tf(float f) {
    uint32_t u;
    asm("cvt.rna.tf32.f32 %0, %1;" : "=r"(u) : "f"(f));
    return u;
}
__device__ __forceinline__ float rnd(float f) { return __uint_as_float(f2tf(f)); }

__device__ __forceinline__ void cpa16(void* s, const float* g) {
    uint32_t sa = (uint32_t)__cvta_generic_to_shared(s);
    asm volatile("cp.async.cg.shared.global [%0], [%1], 16;" :: "r"(sa), "l"(g));
}
#define CP_COMMIT() asm volatile("cp.async.commit_group;")
#define CP_WAIT0()  asm volatile("cp.async.wait_group 0;")

#define MMA_TF32(c, a, b0, b1)                                                 \
    asm volatile(                                                              \
        "mma.sync.aligned.m16n8k8.row.col.f32.tf32.tf32.f32 "                  \
        "{%0,%1,%2,%3},{%4,%5,%6,%7},{%8,%9},{%0,%1,%2,%3};"                   \
        : "+f"(c[0]), "+f"(c[1]), "+f"(c[2]), "+f"(c[3])                       \
        : "r"(a[0]), "r"(a[1]), "r"(a[2]), "r"(a[3]), "r"(b0), "r"(b1));

#define ACC_INIT()                                                             \
    float acc[2][8][4];                                                        \
    _Pragma("unroll")                                                          \
    for (int i = 0; i < 2; i++)                                                \
        _Pragma("unroll")                                                      \
        for (int j = 0; j < 8; j++)                                            \
            _Pragma("unroll")                                                  \
            for (int k = 0; k < 4; k++) acc[i][j][k] = 0.f;

// Compute one BK=32 tile. As: [rows][AST] m-major. Bs: [32][BST] k-major.
#define TILE_COMPUTE_KN(As, Bs)                                                \
    _Pragma("unroll")                                                          \
    for (int kk = 0; kk < 4; kk++) {                                           \
        uint32_t af[2][4];                                                     \
        _Pragma("unroll")                                                      \
        for (int mi = 0; mi < 2; mi++) {                                       \
            int mr = wm + mi * 16 + g;                                         \
            af[mi][0] = (As)[mr * AST + kk * 8 + t];                           \
            af[mi][1] = (As)[(mr + 8) * AST + kk * 8 + t];                     \
            af[mi][2] = (As)[mr * AST + kk * 8 + t + 4];                       \
            af[mi][3] = (As)[(mr + 8) * AST + kk * 8 + t + 4];                 \
        }                                                                      \
        _Pragma("unroll")                                                      \
        for (int ni = 0; ni < 8; ni++) {                                       \
            uint32_t b0 = (Bs)[(kk * 8 + t) * BST + wn + ni * 8 + g];          \
            uint32_t b1 = (Bs)[(kk * 8 + t + 4) * BST + wn + ni * 8 + g];      \
            MMA_TF32(acc[0][ni], af[0], b0, b1);                               \
            MMA_TF32(acc[1][ni], af[1], b0, b1);                               \
        }                                                                      \
    }

// B staged n-major [BN][AST] (scores: K rows n-major).
#define TILE_COMPUTE_NK(As, Bs2)                                               \
    _Pragma("unroll")                                                          \
    for (int kk = 0; kk < 4; kk++) {                                           \
        uint32_t af[2][4];                                                     \
        _Pragma("unroll")                                                      \
        for (int mi = 0; mi < 2; mi++) {                                       \
            int mr = wm + mi * 16 + g;                                         \
            af[mi][0] = (As)[mr * AST + kk * 8 + t];                           \
            af[mi][1] = (As)[(mr + 8) * AST + kk * 8 + t];                     \
            af[mi][2] = (As)[mr * AST + kk * 8 + t + 4];                       \
            af[mi][3] = (As)[(mr + 8) * AST + kk * 8 + t + 4];                 \
        }                                                                      \
        _Pragma("unroll")                                                      \
        for (int ni = 0; ni < 8; ni++) {                                       \
            int nr = wn + ni * 8 + g;                                          \
            uint32_t b0 = (Bs2)[nr * AST + kk * 8 + t];                        \
            uint32_t b1 = (Bs2)[nr * AST + kk * 8 + t + 4];                    \
            MMA_TF32(acc[0][ni], af[0], b0, b1);                               \
            MMA_TF32(acc[1][ni], af[1], b0, b1);                               \
        }                                                                      \
    }

#define STAGE_A_ASY(DST, NT, PTR_EXPR)                                         \
    _Pragma("unroll")                                                          \
    for (int i = 0; i < (128 * 32 / 4) / NT; i++) {                            \
        int v = tid + i * NT, r = v >> 3, kv = (v & 7) * 4;                    \
        cpa16((DST) + r * AST + kv, PTR_EXPR);                                 \
    }
#define STAGE_B_ASY(DST, NT, PTR_EXPR)                                         \
    _Pragma("unroll")                                                          \
    for (int i = 0; i < (32 * 128 / 4) / NT; i++) {                            \
        int v = tid + i * NT, r = v >> 5, nv = (v & 31) * 4;                   \
        cpa16((DST) + r * BST + nv, PTR_EXPR);                                 \
    }
#define STAGE_B_NK_ASY(DST, NT, PTR_EXPR)                                      \
    _Pragma("unroll")                                                          \
    for (int i = 0; i < (128 * 32 / 4) / NT; i++) {                            \
        int v = tid + i * NT, r = v >> 3, kv = (v & 7) * 4;                    \
        cpa16((DST) + r * AST + kv, PTR_EXPR);                                 \
    }

// ---------------------------------------------------------------------------
// 0) round pre-pass: dst[i] = tf32_rna(src[i])
// ---------------------------------------------------------------------------
__global__ __launch_bounds__(256)
void round_kernel(const float* __restrict__ src, float* __restrict__ dst, int n4)
{
    int i = blockIdx.x * 256 + threadIdx.x;
    if (i < n4) {
        float4 f = ((const float4*)src)[i];
        ((uint4*)dst)[i] = make_uint4(f2tf(f.x), f2tf(f.y), f2tf(f.z), f2tf(f.w));
    }
}

// ---------------------------------------------------------------------------
// 1) qkv = gather(embed_r, x) @ qkvw_r + b    M=8192 N=1536 K=512
// ---------------------------------------------------------------------------
__global__ __launch_bounds__(256, 2)
void qkv_kernel(const int* __restrict__ x, const float* __restrict__ bias)
{
    extern __shared__ uint32_t sm[];
    int*      rows = (int*)sm;
    uint32_t* Ab   = sm + 128;
    uint32_t* Bb   = Ab + 2 * BM * AST;
    const int tid = threadIdx.x;
    const int lane = tid & 31, wid = tid >> 5;
    const int wm = (wid & 3) * 32, wn = (wid >> 2) * 64;
    const int g = lane >> 2, t = lane & 3;
    ACC_INIT();
    const int m0 = blockIdx.y * BM;
    const int n0 = blockIdx.x * BN;
    if (tid < BM) rows[tid] = x[m0 + tid];
    __syncthreads();

    STAGE_A_ASY(Ab, 256, g_embed_r + (size_t)rows[r] * DIM + kv);
    STAGE_B_ASY(Bb, 256, g_qkvw_r + (size_t)r * NQKV + n0 + nv);
    CP_COMMIT();

    for (int c = 0; c < 16; c++) {
        const int b = c & 1;
        CP_WAIT0();
        __syncthreads();
        if (c + 1 < 16) {
            const int k1 = (c + 1) * BK;
            uint32_t* An = Ab + (b ^ 1) * BM * AST;
            uint32_t* Bn = Bb + (b ^ 1) * BK * BST;
            STAGE_A_ASY(An, 256, g_embed_r + (size_t)rows[r] * DIM + k1 + kv);
            STAGE_B_ASY(Bn, 256, g_qkvw_r + (size_t)(k1 + r) * NQKV + n0 + nv);
            CP_COMMIT();
        }
        TILE_COMPUTE_KN(Ab + b * BM * AST, Bb + b * BK * BST);
    }
    #pragma unroll
    for (int mi = 0; mi < 2; mi++)
        #pragma unroll
        for (int ni = 0; ni < 8; ni++) {
            int r0 = m0 + wm + mi * 16 + g;
            int c  = n0 + wn + ni * 8 + t * 2;
            float b0 = bias[c], b1 = bias[c + 1];
            float* p0 = g_qkv + (size_t)r0 * NQKV + c;
            float* p1 = g_qkv + (size_t)(r0 + 8) * NQKV + c;
            *(float2*)p0 = make_float2(rnd(acc[mi][ni][0] + b0),
                                       rnd(acc[mi][ni][1] + b1));
            *(float2*)p1 = make_float2(rnd(acc[mi][ni][2] + b0),
                                       rnd(acc[mi][ni][3] + b1));
        }
}

// ---------------------------------------------------------------------------
// 2) scores = Q @ K^T * scale   (lower-triangular blocks only)
// ---------------------------------------------------------------------------
__global__ __launch_bounds__(256, 2)
void scores_kernel()
{
    if (blockIdx.x > blockIdx.y) return;
    extern __shared__ uint32_t sm[];
    uint32_t* Ab = sm;
    uint32_t* Bb = Ab + 2 * BM * AST;
    const int tid = threadIdx.x;
    const int lane = tid & 31, wid = tid >> 5;
    const int wm = (wid & 3) * 32, wn = (wid >> 2) * 64;
    const int g = lane >> 2, t = lane & 3;
    ACC_INIT();
    const int b  = blockIdx.z;
    const int q0 = blockIdx.y * BM;
    const int n0 = blockIdx.x * BN;
    const float* Q = g_qkv + (size_t)(b * SEQ) * NQKV;
    const float* K = Q + DIM;

    STAGE_A_ASY(Ab, 256, Q + (size_t)(q0 + r) * NQKV + kv);
    STAGE_B_NK_ASY(Bb, 256, K + (size_t)(n0 + r) * NQKV + kv);
    CP_COMMIT();

    for (int c = 0; c < 16; c++) {
        const int bf = c & 1;
        CP_WAIT0();
        __syncthreads();
        if (c + 1 < 16) {
            const int k1 = (c + 1) * BK;
            uint32_t* An = Ab + (bf ^ 1) * BM * AST;
            uint32_t* Bn = Bb + (bf ^ 1) * BM * AST;
            STAGE_A_ASY(An, 256, Q + (size_t)(q0 + r) * NQKV + k1 + kv);
            STAGE_B_NK_ASY(Bn, 256, K + (size_t)(n0 + r) * NQKV + k1 + kv);
            CP_COMMIT();
        }
        TILE_COMPUTE_NK(Ab + bf * BM * AST, Bb + bf * BM * AST);
    }
    const float scale = 0.044194173824159216f;
    #pragma unroll
    for (int mi = 0; mi < 2; mi++)
        #pragma unroll
        for (int ni = 0; ni < 8; ni++) {
            int r0 = q0 + wm + mi * 16 + g;
            int c  = n0 + wn + ni * 8 + t * 2;
            float* p0 = g_scores + (size_t)(b * SEQ + r0) * SEQ + c;
            float* p1 = p0 + (size_t)8 * SEQ;
            *(float2*)p0 = make_float2(acc[mi][ni][0] * scale, acc[mi][ni][1] * scale);
            *(float2*)p1 = make_float2(acc[mi][ni][2] * scale, acc[mi][ni][3] * scale);
        }
}

// ---------------------------------------------------------------------------
// 3) causal softmax, smem-resident exp; zero only intra-tile masked strip
//    (attnv reads only k < (q & ~127) + 128 for row q)
// ---------------------------------------------------------------------------
__global__ __launch_bounds__(256)
void softmax_kernel()
{
    const int row = blockIdx.x;
    const int q = row & (SEQ - 1);
    float* p = g_scores + (size_t)row * SEQ;
    const int L = q + 1;
    const int kend = (q & ~127) + 128;
    const int tid = threadIdx.x;
    const int lane = tid & 31, wid = tid >> 5;
    __shared__ float red[8];
    __shared__ float ebuf[SEQ];               // 8 KB exp stash

    float m = -1e30f;
    for (int k = tid; k < L; k += 256) {
        float v = p[k];
        ebuf[k] = v;
        m = fmaxf(m, v);
    }
    #pragma unroll
    for (int s = 16; s > 0; s >>= 1) m = fmaxf(m, __shfl_xor_sync(~0u, m, s));
    if (lane == 0) red[wid] = m;
    __syncthreads();
    m = red[lane & 7];
    #pragma unroll
    for (int s = 4; s > 0; s >>= 1) m = fmaxf(m, __shfl_xor_sync(~0u, m, s));

    float sum = 0.f;
    for (int k = tid; k < L; k += 256) {
        float e = __expf(ebuf[k] - m);
        ebuf[k] = e;
        sum += e;
    }
    #pragma unroll
    for (int s = 16; s > 0; s >>= 1) sum += __shfl_xor_sync(~0u, sum, s);
    __syncthreads();
    if (lane == 0) red[wid] = sum;
    __syncthreads();
    sum = red[lane & 7];
    #pragma unroll
    for (int s = 4; s > 0; s >>= 1) sum += __shfl_xor_sync(~0u, sum, s);

    const float inv = 1.0f / sum;
    for (int k = tid; k < L; k += 256) p[k] = rnd(ebuf[k] * inv);
    for (int k = L + tid; k < kend; k += 256) p[k] = 0.f;
}

// ---------------------------------------------------------------------------
// 4) out = attn @ V   (k truncated at causal boundary q0+128)
// ---------------------------------------------------------------------------
__global__ __launch_bounds__(256, 2)
void attnv_kernel()
{
    extern __shared__ uint32_t sm[];
    uint32_t* Ab = sm;
    uint32_t* Bb = Ab + 2 * BM * AST;
    const int tid = threadIdx.x;
    const int lane = tid & 31, wid = tid >> 5;
    const int wm = (wid & 3) * 32, wn = (wid >> 2) * 64;
    const int g = lane >> 2, t = lane & 3;
    ACC_INIT();
    const int b  = blockIdx.z;
    const int q0 = blockIdx.y * BM;
    const int n0 = blockIdx.x * BN;
    const float* A  = g_scores + (size_t)(b * SEQ) * SEQ;
    const float* Vm = g_qkv + (size_t)(b * SEQ) * NQKV + 2 * DIM;

    STAGE_A_ASY(Ab, 256, A + (size_t)(q0 + r) * SEQ + kv);
    STAGE_B_ASY(Bb, 256, Vm + (size_t)r * NQKV + n0 + nv);
    CP_COMMIT();

    const int NC = (q0 + BM) / BK;
    for (int c = 0; c < NC; c++) {
        const int bf = c & 1;
        CP_WAIT0();
        __syncthreads();
        if (c + 1 < NC) {
            const int k1 = (c + 1) * BK;
            uint32_t* An = Ab + (bf ^ 1) * BM * AST;
            uint32_t* Bn = Bb + (bf ^ 1) * BK * BST;
            STAGE_A_ASY(An, 256, A + (size_t)(q0 + r) * SEQ + k1 + kv);
            STAGE_B_ASY(Bn, 256, Vm + (size_t)(k1 + r) * NQKV + n0 + nv);
            CP_COMMIT();
        }
        TILE_COMPUTE_KN(Ab + bf * BM * AST, Bb + bf * BK * BST);
    }
    #pragma unroll
    for (int mi = 0; mi < 2; mi++)
        #pragma unroll
        for (int ni = 0; ni < 8; ni++) {
            int r0 = q0 + wm + mi * 16 + g;
            int c  = n0 + wn + ni * 8 + t * 2;
            float* p0 = g_attn_out + (size_t)(b * SEQ + r0) * DIM + c;
            float* p1 = p0 + (size_t)8 * DIM;
            *(float2*)p0 = make_float2(rnd(acc[mi][ni][0]), rnd(acc[mi][ni][1]));
            *(float2*)p1 = make_float2(rnd(acc[mi][ni][2]), rnd(acc[mi][ni][3]));
        }
}

// ---------------------------------------------------------------------------
// 5) logits = attn_out @ fcw_r + fc_b    M=8192 N=32000 K=512
//    256x128 tile, 512 threads (8m x 2n warps), BK=64 chunks (8 total).
// ---------------------------------------------------------------------------
#define LBM  256
#define LBK  64
#define LAST 68

__global__ __launch_bounds__(512, 1)
void logits_kernel(const float* __restrict__ bias, float* __restrict__ out)
{
    extern __shared__ uint32_t sm[];
    uint32_t* Ab = sm;                        // 2 * LBM*LAST
    uint32_t* Bb = Ab + 2 * LBM * LAST;       // 2 * LBK*BST
    const int tid = threadIdx.x;
    const int lane = tid & 31, wid = tid >> 5;
    const int wm = (wid & 7) * 32, wn = (wid >> 3) * 64;
    const int g = lane >> 2, t = lane & 3;
    ACC_INIT();
    const int m0 = blockIdx.y * LBM;
    const int n0 = blockIdx.x * BN;

    #pragma unroll
    for (int i = 0; i < 8; i++) {
        int v = tid + i * 512, r = v >> 4, kv = (v & 15) * 4;
        cpa16(Ab + r * LAST + kv, g_attn_out + (size_t)(m0 + r) * DIM + kv);
    }
    #pragma unroll
    for (int i = 0; i < 4; i++) {
        int v = tid + i * 512, r = v >> 5, nv = (v & 31) * 4;
        cpa16(Bb + r * BST + nv, g_fcw_r + (size_t)r * VOCAB + n0 + nv);
    }
    CP_COMMIT();

    for (int c = 0; c < 8; c++) {
        const int bf = c & 1;
        CP_WAIT0();
        __syncthreads();
        if (c + 1 < 8) {
            const int k1 = (c + 1) * LBK;
            uint32_t* An = Ab + (bf ^ 1) * LBM * LAST;
            uint32_t* Bn = Bb + (bf ^ 1) * LBK * BST;
            #pragma unroll
            for (int i = 0; i < 8; i++) {
                int v = tid + i * 512, r = v >> 4, kv = (v & 15) * 4;
                cpa16(An + r * LAST + kv,
                      g_attn_out + (size_t)(m0 + r) * DIM + k1 + kv);
            }
            #pragma unroll
            for (int i = 0; i < 4; i++) {
                int v = tid + i * 512, r = v >> 5, nv = (v & 31) * 4;
                cpa16(Bn + r * BST + nv,
                      g_fcw_r + (size_t)(k1 + r) * VOCAB + n0 + nv);
            }
            CP_COMMIT();
        }
        const uint32_t* As = Ab + bf * LBM * LAST;
        const uint32_t* Bs = Bb + bf * LBK * BST;
        #pragma unroll
        for (int kk = 0; kk < 8; kk++) {
            uint32_t af[2][4];
            #pragma unroll
            for (int mi = 0; mi < 2; mi++) {
                int mr = wm + mi * 16 + g;
                af[mi][0] = As[mr * LAST + kk * 8 + t];
                af[mi][1] = As[(mr + 8) * LAST + kk * 8 + t];
                af[mi][2] = As[mr * LAST + kk * 8 + t + 4];
                af[mi][3] = As[(mr + 8) * LAST + kk * 8 + t + 4];
            }
            #pragma unroll
            for (int ni = 0; ni < 8; ni++) {
                uint32_t b0 = Bs[(kk * 8 + t) * BST + wn + ni * 8 + g];
                uint32_t b1 = Bs[(kk * 8 + t + 4) * BST + wn + ni * 8 + g];
                MMA_TF32(acc[0][ni], af[0], b0, b1);
                MMA_TF32(acc[1][ni], af[1], b0, b1);
            }
        }
    }
    #pragma unroll
    for (int mi = 0; mi < 2; mi++)
        #pragma unroll
        for (int ni = 0; ni < 8; ni++) {
            int r0 = m0 + wm + mi * 16 + g;
            int c  = n0 + wn + ni * 8 + t * 2;
            float b0 = bias[c], b1 = bias[c + 1];
            float* p0 = out + (size_t)r0 * VOCAB + c;
            float* p1 = out + (size_t)(r0 + 8) * VOCAB + c;
            *(float2*)p0 = make_float2(acc[mi][ni][0] + b0, acc[mi][ni][1] + b1);
            *(float2*)p1 = make_float2(acc[mi][ni][2] + b0, acc[mi][ni][3] + b1);
        }
}

// ---------------------------------------------------------------------------
extern "C" void kernel_launch(void* const* d_in, const int* in_sizes, int n_in,
                              void* d_out, int out_size)
{
    (void)in_sizes; (void)n_in; (void)out_size;
    const int*   x     = (const int*)  d_in[0];
    const float* embed = (const float*)d_in[1];
    const float* qkv_w = (const float*)d_in[2];
    const float* qkv_b = (const float*)d_in[3];
    const float* fc_w  = (const float*)d_in[4];
    const float* fc_b  = (const float*)d_in[5];
    float* out = (float*)d_out;

    const int smem_qkv    = (128 + 2 * BM * AST + 2 * BK * BST) * 4;
    const int smem_scores = (2 * BM * AST + 2 * BM * AST) * 4;
    const int smem_attnv  = (2 * BM * AST + 2 * BK * BST) * 4;
    const int smem_logits = (2 * LBM * LAST + 2 * LBK * BST) * 4;   // ~209 KB

    cudaFuncSetAttribute(qkv_kernel,
        cudaFuncAttributeMaxDynamicSharedMemorySize, smem_qkv);
    cudaFuncSetAttribute(scores_kernel,
        cudaFuncAttributeMaxDynamicSharedMemorySize, smem_scores);
    cudaFuncSetAttribute(attnv_kernel,
        cudaFuncAttributeMaxDynamicSharedMemorySize, smem_attnv);
    cudaFuncSetAttribute(logits_kernel,
        cudaFuncAttributeMaxDynamicSharedMemorySize, smem_logits);

    float* emb_dst;  cudaGetSymbolAddress((void**)&emb_dst,  g_embed_r);
    float* qkvw_dst; cudaGetSymbolAddress((void**)&qkvw_dst, g_qkvw_r);
    float* fcw_dst;  cudaGetSymbolAddress((void**)&fcw_dst,  g_fcw_r);
    const int n4_emb  = VOCAB * DIM / 4;
    const int n4_qkvw = DIM * NQKV / 4;
    const int n4_fcw  = DIM * VOCAB / 4;
    round_kernel<<<(n4_emb  + 255) / 256, 256>>>(embed, emb_dst,  n4_emb);
    round_kernel<<<(n4_qkvw + 255) / 256, 256>>>(qkv_w, qkvw_dst, n4_qkvw);
    round_kernel<<<(n4_fcw  + 255) / 256, 256>>>(fc_w,  fcw_dst,  n4_fcw);

    qkv_kernel    <<<dim3(NQKV / BN, MTOK / BM), 256, smem_qkv>>>(x, qkv_b);
    scores_kernel <<<dim3(SEQ / BN, SEQ / BM, BATCH), 256, smem_scores>>>();
    softmax_kernel<<<MTOK, 256>>>();
    attnv_kernel  <<<dim3(DIM / BN, SEQ / BM, BATCH), 256, smem_attnv>>>();
    logits_kernel <<<dim3(VOCAB / BN, MTOK / LBM), 512, smem_logits>>>(fc_b, out);
}

// round 12
// speedup vs baseline: 1.9842x; 1.4613x over previous
#include <cuda_runtime.h>
#include <cuda_fp16.h>
#include <cstdint>
#include <cstddef>

// ---------------------------------------------------------------------------
// TinyTransformer B=4 S=2048 D=512 V=32000 — fp16 mma.sync m16n8k16 (f32 acc).
// fp16 mantissa == tf32 mantissa (11 bits) and all activations are O(1) or
// smaller -> same error class as tf32 at 2x tensor throughput, half traffic.
// All GEMMs: A [M][K] m-major, B [N][K] n-major, K contiguous (fp16x2 regs).
// Smem row stride 20 words (== 4 mod 32): conflict-free fragment loads.
// R7-proven wait0 double-buffer loop structure.
// ---------------------------------------------------------------------------

#define BATCH 4
#define SEQ   2048
#define DIM   512
#define VOCAB 32000
#define NQKV  1536
#define MTOK  8192
#define QKW   1024           // Q|K width in g_qkvh

#define BM 128
#define BN 128
#define BK 32                // 32 halves per chunk (64 B/row)
#define HST 20               // smem row stride, 32-bit words (16 data + 4 pad)

__device__ __align__(256) __half g_qkvh[(size_t)MTOK * QKW];        // Q|K
__device__ __align__(256) __half g_vT[(size_t)BATCH * DIM * SEQ];   // V^T
__device__ float  g_scores[(size_t)BATCH * SEQ * SEQ];
__device__ __align__(256) __half g_attn[(size_t)BATCH * SEQ * SEQ];
__device__ __align__(256) __half g_attn_out[(size_t)MTOK * DIM];
__device__ __align__(256) __half g_embed_h[(size_t)VOCAB * DIM];
__device__ __align__(256) __half g_qkvwT[(size_t)NQKV * DIM];
__device__ __align__(256) __half g_fcwT[(size_t)VOCAB * DIM];

__device__ __forceinline__ void cpa16(void* s, const void* g) {
    uint32_t sa = (uint32_t)__cvta_generic_to_shared(s);
    asm volatile("cp.async.cg.shared.global [%0], [%1], 16;" :: "r"(sa), "l"(g));
}
#define CP_COMMIT() asm volatile("cp.async.commit_group;")
#define CP_WAIT0()  asm volatile("cp.async.wait_group 0;")

#define MMA_F16(c, a, b0, b1)                                                  \
    asm volatile(                                                              \
        "mma.sync.aligned.m16n8k16.row.col.f32.f16.f16.f32 "                   \
        "{%0,%1,%2,%3},{%4,%5,%6,%7},{%8,%9},{%0,%1,%2,%3};"                   \
        : "+f"(c[0]), "+f"(c[1]), "+f"(c[2]), "+f"(c[3])                       \
        : "r"(a[0]), "r"(a[1]), "r"(a[2]), "r"(a[3]), "r"(b0), "r"(b1));

#define ACC_INIT()                                                             \
    float acc[2][8][4];                                                        \
    _Pragma("unroll")                                                          \
    for (int i = 0; i < 2; i++)                                                \
        _Pragma("unroll")                                                      \
        for (int j = 0; j < 8; j++)                                            \
            _Pragma("unroll")                                                  \
            for (int k = 0; k < 4; k++) acc[i][j][k] = 0.f;

// One BK=32 chunk = 2 x (K=16) MMA steps. As: [m][HST], Bs: [n][HST].
// a0={A[g][2t],A[g][2t+1]} -> word t; a2 -> word t+4 (k=2t+8); rows g/g+8.
// b0={B[2t][g],B[2t+1][g]} -> word (g-row, t); b1 -> word t+4.
#define TILE_COMPUTE_H(As, Bs)                                                 \
    _Pragma("unroll")                                                          \
    for (int kk = 0; kk < 2; kk++) {                                           \
        uint32_t af[2][4];                                                     \
        _Pragma("unroll")                                                      \
        for (int mi = 0; mi < 2; mi++) {                                       \
            int mr = wm + mi * 16 + g;                                         \
            af[mi][0] = (As)[mr * HST + kk * 8 + t];                           \
            af[mi][1] = (As)[(mr + 8) * HST + kk * 8 + t];                     \
            af[mi][2] = (As)[mr * HST + kk * 8 + t + 4];                       \
            af[mi][3] = (As)[(mr + 8) * HST + kk * 8 + t + 4];                 \
        }                                                                      \
        _Pragma("unroll")                                                      \
        for (int ni = 0; ni < 8; ni++) {                                       \
            int nr = wn + ni * 8 + g;                                          \
            uint32_t b0 = (Bs)[nr * HST + kk * 8 + t];                         \
            uint32_t b1 = (Bs)[nr * HST + kk * 8 + t + 4];                     \
            MMA_F16(acc[0][ni], af[0], b0, b1);                                \
            MMA_F16(acc[1][ni], af[1], b0, b1);                                \
        }                                                                      \
    }

// Stage ROWS x 32 halves (64 B/row = 4 x 16 B). PTR_EXPR uses r (row), hh
// (half offset within row).
#define STAGE_H(DST, NT, ROWS, PTR_EXPR)                                       \
    _Pragma("unroll")                                                          \
    for (int i = 0; i < (ROWS * 4) / NT; i++) {                                \
        int v = tid + i * NT, r = v >> 2, hh = (v & 3) * 8;                    \
        cpa16((DST) + r * HST + (v & 3) * 4, PTR_EXPR);                        \
    }

// ---------------------------------------------------------------------------
// 0a) fp32 -> fp16 elementwise (embed)
// ---------------------------------------------------------------------------
__global__ __launch_bounds__(256)
void cvt_half_kernel(const float* __restrict__ src, __half* __restrict__ dst,
                     int n4)
{
    int i = blockIdx.x * 256 + threadIdx.x;
    if (i < n4) {
        float4 f = ((const float4*)src)[i];
        __half2 h0 = __floats2half2_rn(f.x, f.y);
        __half2 h1 = __floats2half2_rn(f.z, f.w);
        ((__half2*)dst)[i * 2]     = h0;
        ((__half2*)dst)[i * 2 + 1] = h1;
    }
}

// ---------------------------------------------------------------------------
// 0b) weights: transpose + cvt   src fp32 [DIM][ncols] -> dst fp16 [ncols][DIM]
// ---------------------------------------------------------------------------
__global__ __launch_bounds__(256)
void transpose_cvt_kernel(const float* __restrict__ src,
                          __half* __restrict__ dst, int ncols)
{
    __shared__ float tile[32][33];
    const int c0 = blockIdx.x * 32;
    const int r0 = blockIdx.y * 32;
    const int xx = threadIdx.x & 31, yy = threadIdx.x >> 5;
    #pragma unroll
    for (int i = 0; i < 32; i += 8)
        tile[yy + i][xx] = src[(size_t)(r0 + yy + i) * ncols + c0 + xx];
    __syncthreads();
    #pragma unroll
    for (int i = 0; i < 32; i += 8)
        dst[(size_t)(c0 + yy + i) * DIM + r0 + xx] =
            __float2half_rn(tile[xx][yy + i]);
}

// ---------------------------------------------------------------------------
// 1) qkv = gather(embed,x) @ qkv_w + b.  Q/K -> g_qkvh fp16; V -> g_vT fp16.
// ---------------------------------------------------------------------------
__global__ __launch_bounds__(256, 2)
void qkv_kernel(const int* __restrict__ x, const float* __restrict__ bias)
{
    extern __shared__ uint32_t sm[];
    int*      rows = (int*)sm;
    uint32_t* Ab   = sm + 128;                 // 2 * BM*HST
    uint32_t* Bb   = Ab + 2 * BM * HST;        // 2 * BM*HST
    const int tid = threadIdx.x;
    const int lane = tid & 31, wid = tid >> 5;
    const int wm = (wid & 3) * 32, wn = (wid >> 2) * 64;
    const int g = lane >> 2, t = lane & 3;
    ACC_INIT();
    const int m0 = blockIdx.y * BM;
    const int n0 = blockIdx.x * BN;
    if (tid < BM) rows[tid] = x[m0 + tid];
    __syncthreads();

    STAGE_H(Ab, 256, 128, g_embed_h + (size_t)rows[r] * DIM + hh);
    STAGE_H(Bb, 256, 128, g_qkvwT + (size_t)(n0 + r) * DIM + hh);
    CP_COMMIT();

    for (int c = 0; c < 16; c++) {
        const int bf = c & 1;
        CP_WAIT0();
        __syncthreads();
        if (c + 1 < 16) {
            const int k1 = (c + 1) * BK;
            uint32_t* An = Ab + (bf ^ 1) * BM * HST;
            uint32_t* Bn = Bb + (bf ^ 1) * BM * HST;
            STAGE_H(An, 256, 128, g_embed_h + (size_t)rows[r] * DIM + k1 + hh);
            STAGE_H(Bn, 256, 128, g_qkvwT + (size_t)(n0 + r) * DIM + k1 + hh);
            CP_COMMIT();
        }
        TILE_COMPUTE_H(Ab + bf * BM * HST, Bb + bf * BM * HST);
    }
    #pragma unroll
    for (int mi = 0; mi < 2; mi++)
        #pragma unroll
        for (int ni = 0; ni < 8; ni++) {
            int r0 = m0 + wm + mi * 16 + g;
            int c  = n0 + wn + ni * 8 + t * 2;
            float b0 = bias[c], b1 = bias[c + 1];
            float v0 = acc[mi][ni][0] + b0, v1 = acc[mi][ni][1] + b1;
            float v2 = acc[mi][ni][2] + b0, v3 = acc[mi][ni][3] + b1;
            if (n0 < QKW) {                      // Q | K -> [tok][1024]
                *(__half2*)(g_qkvh + (size_t)r0 * QKW + c) =
                    __floats2half2_rn(v0, v1);
                *(__half2*)(g_qkvh + (size_t)(r0 + 8) * QKW + c) =
                    __floats2half2_rn(v2, v3);
            } else {                             // V -> V^T [b][d][s]
                int d = c - QKW, bb = r0 >> 11, s = r0 & (SEQ - 1);
                __half* base = g_vT + (size_t)bb * DIM * SEQ;
                base[(size_t)d * SEQ + s]           = __float2half_rn(v0);
                base[(size_t)(d + 1) * SEQ + s]     = __float2half_rn(v1);
                base[(size_t)d * SEQ + s + 8]       = __float2half_rn(v2);
                base[(size_t)(d + 1) * SEQ + s + 8] = __float2half_rn(v3);
            }
        }
}

// ---------------------------------------------------------------------------
// 2) scores = Q @ K^T * scale  (lower-triangular blocks only), fp32 out
// ---------------------------------------------------------------------------
__global__ __launch_bounds__(256, 2)
void scores_kernel()
{
    if (blockIdx.x > blockIdx.y) return;
    extern __shared__ uint32_t sm[];
    uint32_t* Ab = sm;
    uint32_t* Bb = Ab + 2 * BM * HST;
    const int tid = threadIdx.x;
    const int lane = tid & 31, wid = tid >> 5;
    const int wm = (wid & 3) * 32, wn = (wid >> 2) * 64;
    const int g = lane >> 2, t = lane & 3;
    ACC_INIT();
    const int b  = blockIdx.z;
    const int q0 = blockIdx.y * BM;
    const int n0 = blockIdx.x * BN;
    const __half* Q = g_qkvh + (size_t)(b * SEQ) * QKW;
    const __half* K = Q + DIM;

    STAGE_H(Ab, 256, 128, Q + (size_t)(q0 + r) * QKW + hh);
    STAGE_H(Bb, 256, 128, K + (size_t)(n0 + r) * QKW + hh);
    CP_COMMIT();

    for (int c = 0; c < 16; c++) {
        const int bf = c & 1;
        CP_WAIT0();
        __syncthreads();
        if (c + 1 < 16) {
            const int k1 = (c + 1) * BK;
            uint32_t* An = Ab + (bf ^ 1) * BM * HST;
            uint32_t* Bn = Bb + (bf ^ 1) * BM * HST;
            STAGE_H(An, 256, 128, Q + (size_t)(q0 + r) * QKW + k1 + hh);
            STAGE_H(Bn, 256, 128, K + (size_t)(n0 + r) * QKW + k1 + hh);
            CP_COMMIT();
        }
        TILE_COMPUTE_H(Ab + bf * BM * HST, Bb + bf * BM * HST);
    }
    const float scale = 0.044194173824159216f;
    #pragma unroll
    for (int mi = 0; mi < 2; mi++)
        #pragma unroll
        for (int ni = 0; ni < 8; ni++) {
            int r0 = q0 + wm + mi * 16 + g;
            int c  = n0 + wn + ni * 8 + t * 2;
            float* p0 = g_scores + (size_t)(b * SEQ + r0) * SEQ + c;
            float* p1 = p0 + (size_t)8 * SEQ;
            *(float2*)p0 = make_float2(acc[mi][ni][0] * scale, acc[mi][ni][1] * scale);
            *(float2*)p1 = make_float2(acc[mi][ni][2] * scale, acc[mi][ni][3] * scale);
        }
}

// ---------------------------------------------------------------------------
// 3) causal softmax: read fp32 scores, write fp16 attn; zero [L, kend)
// ---------------------------------------------------------------------------
__global__ __launch_bounds__(256)
void softmax_kernel()
{
    const int row = blockIdx.x;
    const int q = row & (SEQ - 1);
    const float* p = g_scores + (size_t)row * SEQ;
    __half* pa = g_attn + (size_t)row * SEQ;
    const int L = q + 1;
    const int kend = (q & ~127) + 128;
    const int tid = threadIdx.x;
    const int lane = tid & 31, wid = tid >> 5;
    __shared__ float red[8];
    __shared__ float ebuf[SEQ];

    float m = -1e30f;
    for (int k = tid; k < L; k += 256) {
        float v = p[k];
        ebuf[k] = v;
        m = fmaxf(m, v);
    }
    #pragma unroll
    for (int s = 16; s > 0; s >>= 1) m = fmaxf(m, __shfl_xor_sync(~0u, m, s));
    if (lane == 0) red[wid] = m;
    __syncthreads();
    m = red[lane & 7];
    #pragma unroll
    for (int s = 4; s > 0; s >>= 1) m = fmaxf(m, __shfl_xor_sync(~0u, m, s));

    float sum = 0.f;
    for (int k = tid; k < L; k += 256) {
        float e = __expf(ebuf[k] - m);
        ebuf[k] = e;
        sum += e;
    }
    #pragma unroll
    for (int s = 16; s > 0; s >>= 1) sum += __shfl_xor_sync(~0u, sum, s);
    __syncthreads();
    if (lane == 0) red[wid] = sum;
    __syncthreads();
    sum = red[lane & 7];
    #pragma unroll
    for (int s = 4; s > 0; s >>= 1) sum += __shfl_xor_sync(~0u, sum, s);

    const float inv = 1.0f / sum;
    for (int k = tid; k < L; k += 256) pa[k] = __float2half_rn(ebuf[k] * inv);
    for (int k = L + tid; k < kend; k += 256) pa[k] = __half(0.f);
}

// ---------------------------------------------------------------------------
// 4) out = attn @ V  (B = V^T n-major; k truncated at causal boundary)
// ---------------------------------------------------------------------------
__global__ __launch_bounds__(256, 2)
void attnv_kernel()
{
    extern __shared__ uint32_t sm[];
    uint32_t* Ab = sm;
    uint32_t* Bb = Ab + 2 * BM * HST;
    const int tid = threadIdx.x;
    const int lane = tid & 31, wid = tid >> 5;
    const int wm = (wid & 3) * 32, wn = (wid >> 2) * 64;
    const int g = lane >> 2, t = lane & 3;
    ACC_INIT();
    const int b  = blockIdx.z;
    const int q0 = blockIdx.y * BM;
    const int n0 = blockIdx.x * BN;
    const __half* A  = g_attn + (size_t)(b * SEQ) * SEQ;
    const __half* VT = g_vT + ((size_t)b * DIM + n0) * SEQ;

    STAGE_H(Ab, 256, 128, A + (size_t)(q0 + r) * SEQ + hh);
    STAGE_H(Bb, 256, 128, VT + (size_t)r * SEQ + hh);
    CP_COMMIT();

    const int NC = (q0 + BM) / BK;
    for (int c = 0; c < NC; c++) {
        const int bf = c & 1;
        CP_WAIT0();
        __syncthreads();
        if (c + 1 < NC) {
            const int k1 = (c + 1) * BK;
            uint32_t* An = Ab + (bf ^ 1) * BM * HST;
            uint32_t* Bn = Bb + (bf ^ 1) * BM * HST;
            STAGE_H(An, 256, 128, A + (size_t)(q0 + r) * SEQ + k1 + hh);
            STAGE_H(Bn, 256, 128, VT + (size_t)r * SEQ + k1 + hh);
            CP_COMMIT();
        }
        TILE_COMPUTE_H(Ab + bf * BM * HST, Bb + bf * BM * HST);
    }
    #pragma unroll
    for (int mi = 0; mi < 2; mi++)
        #pragma unroll
        for (int ni = 0; ni < 8; ni++) {
            int r0 = q0 + wm + mi * 16 + g;
            int c  = n0 + wn + ni * 8 + t * 2;
            __half* base = g_attn_out + (size_t)(b * SEQ) * DIM;
            *(__half2*)(base + (size_t)r0 * DIM + c) =
                __floats2half2_rn(acc[mi][ni][0], acc[mi][ni][1]);
            *(__half2*)(base + (size_t)(r0 + 8) * DIM + c) =
                __floats2half2_rn(acc[mi][ni][2], acc[mi][ni][3]);
        }
}

// ---------------------------------------------------------------------------
// 5) logits = attn_out @ fc_w^T + fc_b   256x128 tile, 512 threads, fp32 out
// ---------------------------------------------------------------------------
#define LBM 256
__global__ __launch_bounds__(512, 1)
void logits_kernel(const float* __restrict__ bias, float* __restrict__ out)
{
    extern __shared__ uint32_t sm[];
    uint32_t* Ab = sm;                         // 2 * LBM*HST
    uint32_t* Bb = Ab + 2 * LBM * HST;         // 2 * BM*HST
    const int tid = threadIdx.x;
    const int lane = tid & 31, wid = tid >> 5;
    const int wm = (wid & 7) * 32, wn = (wid >> 3) * 64;
    const int g = lane >> 2, t = lane & 3;
    ACC_INIT();
    const int m0 = blockIdx.y * LBM;
    const int n0 = blockIdx.x * BN;

    STAGE_H(Ab, 512, 256, g_attn_out + (size_t)(m0 + r) * DIM + hh);
    STAGE_H(Bb, 512, 128, g_fcwT + (size_t)(n0 + r) * DIM + hh);
    CP_COMMIT();

    for (int c = 0; c < 16; c++) {
        const int bf = c & 1;
        CP_WAIT0();
        __syncthreads();
        if (c + 1 < 16) {
            const int k1 = (c + 1) * BK;
            uint32_t* An = Ab + (bf ^ 1) * LBM * HST;
            uint32_t* Bn = Bb + (bf ^ 1) * BM * HST;
            STAGE_H(An, 512, 256, g_attn_out + (size_t)(m0 + r) * DIM + k1 + hh);
            STAGE_H(Bn, 512, 128, g_fcwT + (size_t)(n0 + r) * DIM + k1 + hh);
            CP_COMMIT();
        }
        TILE_COMPUTE_H(Ab + bf * LBM * HST, Bb + bf * BM * HST);
    }
    #pragma unroll
    for (int mi = 0; mi < 2; mi++)
        #pragma unroll
        for (int ni = 0; ni < 8; ni++) {
            int r0 = m0 + wm + mi * 16 + g;
            int c  = n0 + wn + ni * 8 + t * 2;
            float b0 = bias[c], b1 = bias[c + 1];
            float* p0 = out + (size_t)r0 * VOCAB + c;
            float* p1 = out + (size_t)(r0 + 8) * VOCAB + c;
            *(float2*)p0 = make_float2(acc[mi][ni][0] + b0, acc[mi][ni][1] + b1);
            *(float2*)p1 = make_float2(acc[mi][ni][2] + b0, acc[mi][ni][3] + b1);
        }
}

// ---------------------------------------------------------------------------
extern "C" void kernel_launch(void* const* d_in, const int* in_sizes, int n_in,
                              void* d_out, int out_size)
{
    (void)in_sizes; (void)n_in; (void)out_size;
    const int*   x     = (const int*)  d_in[0];
    const float* embed = (const float*)d_in[1];
    const float* qkv_w = (const float*)d_in[2];
    const float* qkv_b = (const float*)d_in[3];
    const float* fc_w  = (const float*)d_in[4];
    const float* fc_b  = (const float*)d_in[5];
    float* out = (float*)d_out;

    const int smem_qkv    = (128 + 4 * BM * HST) * 4;          // ~41.5 KB
    const int smem_scores = (4 * BM * HST) * 4;                // ~41 KB
    const int smem_attnv  = (4 * BM * HST) * 4;                // ~41 KB
    const int smem_logits = (2 * LBM * HST + 2 * BM * HST) * 4; // ~61.4 KB

    cudaFuncSetAttribute(qkv_kernel,
        cudaFuncAttributeMaxDynamicSharedMemorySize, smem_qkv);
    cudaFuncSetAttribute(scores_kernel,
        cudaFuncAttributeMaxDynamicSharedMemorySize, smem_scores);
    cudaFuncSetAttribute(attnv_kernel,
        cudaFuncAttributeMaxDynamicSharedMemorySize, smem_attnv);
    cudaFuncSetAttribute(logits_kernel,
        cudaFuncAttributeMaxDynamicSharedMemorySize, smem_logits);

    __half* emb_dst;  cudaGetSymbolAddress((void**)&emb_dst,  g_embed_h);
    __half* qkvw_dst; cudaGetSymbolAddress((void**)&qkvw_dst, g_qkvwT);
    __half* fcw_dst;  cudaGetSymbolAddress((void**)&fcw_dst,  g_fcwT);

    cvt_half_kernel<<<VOCAB * DIM / 4 / 256, 256>>>(embed, emb_dst,
                                                    VOCAB * DIM / 4);
    transpose_cvt_kernel<<<dim3(NQKV / 32, DIM / 32), 256>>>(qkv_w, qkvw_dst, NQKV);
    transpose_cvt_kernel<<<dim3(VOCAB / 32, DIM / 32), 256>>>(fc_w, fcw_dst, VOCAB);

    qkv_kernel    <<<dim3(NQKV / BN, MTOK / BM), 256, smem_qkv>>>(x, qkv_b);
    scores_kernel <<<dim3(SEQ / BN, SEQ / BM, BATCH), 256, smem_scores>>>();
    softmax_kernel<<<MTOK, 256>>>();
    attnv_kernel  <<<dim3(DIM / BN, SEQ / BM, BATCH), 256, smem_attnv>>>();
    logits_kernel <<<dim3(VOCAB / BN, MTOK / LBM), 512, smem_logits>>>(fc_b, out);
}

// round 13
// speedup vs baseline: 2.2204x; 1.1190x over previous
#include <cuda_runtime.h>
#include <cuda_fp16.h>
#include <cstdint>
#include <cstddef>

// ---------------------------------------------------------------------------
// TinyTransformer B=4 S=2048 D=512 V=32000 — fp16 mma.sync m16n8k16 (f32 acc)
// R12: fragment loads via ldmatrix.m8n8.x4 (12 loads per 32-K chunk vs 48
// LDS.32). A [M][K] m-major, B [N][K] n-major, HST=20 stride (conflict-free
// for both scalar and ldmatrix phases). R7 wait0 double-buffer loop.
// ---------------------------------------------------------------------------

#define BATCH 4
#define SEQ   2048
#define DIM   512
#define VOCAB 32000
#define NQKV  1536
#define MTOK  8192
#define QKW   1024

#define BM 128
#define BN 128
#define BK 32                // 32 halves per chunk (64 B/row)
#define HST 20               // smem row stride in 32-bit words

__device__ __align__(256) __half g_qkvh[(size_t)MTOK * QKW];
__device__ __align__(256) __half g_vT[(size_t)BATCH * DIM * SEQ];
__device__ float  g_scores[(size_t)BATCH * SEQ * SEQ];
__device__ __align__(256) __half g_attn[(size_t)BATCH * SEQ * SEQ];
__device__ __align__(256) __half g_attn_out[(size_t)MTOK * DIM];
__device__ __align__(256) __half g_embed_h[(size_t)VOCAB * DIM];
__device__ __align__(256) __half g_qkvwT[(size_t)NQKV * DIM];
__device__ __align__(256) __half g_fcwT[(size_t)VOCAB * DIM];

__device__ __forceinline__ void cpa16(void* s, const void* g) {
    uint32_t sa = (uint32_t)__cvta_generic_to_shared(s);
    asm volatile("cp.async.cg.shared.global [%0], [%1], 16;" :: "r"(sa), "l"(g));
}
#define CP_COMMIT() asm volatile("cp.async.commit_group;")
#define CP_WAIT0()  asm volatile("cp.async.wait_group 0;")

#define MMA_F16(c, a, b0, b1)                                                  \
    asm volatile(                                                              \
        "mma.sync.aligned.m16n8k16.row.col.f32.f16.f16.f32 "                   \
        "{%0,%1,%2,%3},{%4,%5,%6,%7},{%8,%9},{%0,%1,%2,%3};"                   \
        : "+f"(c[0]), "+f"(c[1]), "+f"(c[2]), "+f"(c[3])                       \
        : "r"(a[0]), "r"(a[1]), "r"(a[2]), "r"(a[3]), "r"(b0), "r"(b1));

#define LDSM4(r, addr)                                                         \
    asm volatile("ldmatrix.sync.aligned.m8n8.x4.shared.b16 {%0,%1,%2,%3}, [%4];" \
        : "=r"((r)[0]), "=r"((r)[1]), "=r"((r)[2]), "=r"((r)[3]) : "r"(addr))

#define ACC_INIT()                                                             \
    float acc[2][8][4];                                                        \
    _Pragma("unroll")                                                          \
    for (int i = 0; i < 2; i++)                                                \
        _Pragma("unroll")                                                      \
        for (int j = 0; j < 8; j++)                                            \
            _Pragma("unroll")                                                  \
            for (int k = 0; k < 4; k++) acc[i][j][k] = 0.f;

// Per-lane ldmatrix address components (bytes, relative to tile base):
//   A: rows (wm + (l&7) + ((l>>3)&1)*8), k-halfblock ((l>>4)&1)
//   B: rows (wn + (l&7) + ((l>>4)&1)*8), k-halfblock ((l>>3)&1)
#define LDSM_OFFSETS()                                                         \
    const uint32_t aoff = (uint32_t)(((wm + (lane & 7) + ((lane >> 3) & 1) * 8) \
                         * HST + ((lane >> 4) & 1) * 4) * 4);                  \
    const uint32_t boff = (uint32_t)(((wn + (lane & 7) + ((lane >> 4) & 1) * 8) \
                         * HST + ((lane >> 3) & 1) * 4) * 4);

// One BK=32 chunk via ldmatrix: aA/aB = smem byte addresses of the current
// buffers already including aoff/boff.
#define TILE_LDSM(aA, aB)                                                      \
    _Pragma("unroll")                                                          \
    for (int kk = 0; kk < 2; kk++) {                                           \
        uint32_t a0[4], a1[4];                                                 \
        LDSM4(a0, (aA) + kk * 32);                                             \
        LDSM4(a1, (aA) + 16 * HST * 4 + kk * 32);                              \
        _Pragma("unroll")                                                      \
        for (int p = 0; p < 4; p++) {                                          \
            uint32_t bb[4];                                                    \
            LDSM4(bb, (aB) + p * 16 * HST * 4 + kk * 32);                      \
            MMA_F16(acc[0][2 * p],     a0, bb[0], bb[1]);                      \
            MMA_F16(acc[1][2 * p],     a1, bb[0], bb[1]);                      \
            MMA_F16(acc[0][2 * p + 1], a0, bb[2], bb[3]);                      \
            MMA_F16(acc[1][2 * p + 1], a1, bb[2], bb[3]);                      \
        }                                                                      \
    }

// Stage ROWS x 32 halves (64 B/row = 4 x 16 B).
#define STAGE_H(DST, NT, ROWS, PTR_EXPR)                                       \
    _Pragma("unroll")                                                          \
    for (int i = 0; i < (ROWS * 4) / NT; i++) {                                \
        int v = tid + i * NT, r = v >> 2, hh = (v & 3) * 8;                    \
        cpa16((DST) + r * HST + (v & 3) * 4, PTR_EXPR);                        \
    }

// ---------------------------------------------------------------------------
// 0a) fp32 -> fp16 elementwise (embed)
// ---------------------------------------------------------------------------
__global__ __launch_bounds__(256)
void cvt_half_kernel(const float* __restrict__ src, __half* __restrict__ dst,
                     int n4)
{
    int i = blockIdx.x * 256 + threadIdx.x;
    if (i < n4) {
        float4 f = ((const float4*)src)[i];
        ((__half2*)dst)[i * 2]     = __floats2half2_rn(f.x, f.y);
        ((__half2*)dst)[i * 2 + 1] = __floats2half2_rn(f.z, f.w);
    }
}

// ---------------------------------------------------------------------------
// 0b) weights: transpose + cvt   src fp32 [DIM][ncols] -> dst fp16 [ncols][DIM]
// ---------------------------------------------------------------------------
__global__ __launch_bounds__(256)
void transpose_cvt_kernel(const float* __restrict__ src,
                          __half* __restrict__ dst, int ncols)
{
    __shared__ float tile[32][33];
    const int c0 = blockIdx.x * 32;
    const int r0 = blockIdx.y * 32;
    const int xx = threadIdx.x & 31, yy = threadIdx.x >> 5;
    #pragma unroll
    for (int i = 0; i < 32; i += 8)
        tile[yy + i][xx] = src[(size_t)(r0 + yy + i) * ncols + c0 + xx];
    __syncthreads();
    #pragma unroll
    for (int i = 0; i < 32; i += 8)
        dst[(size_t)(c0 + yy + i) * DIM + r0 + xx] =
            __float2half_rn(tile[xx][yy + i]);
}

// ---------------------------------------------------------------------------
// 1) qkv = gather(embed,x) @ qkv_w + b.  Q/K -> g_qkvh; V -> g_vT.
// ---------------------------------------------------------------------------
__global__ __launch_bounds__(256, 2)
void qkv_kernel(const int* __restrict__ x, const float* __restrict__ bias)
{
    extern __shared__ uint32_t sm[];
    int*      rows = (int*)sm;
    uint32_t* Ab   = sm + 128;
    uint32_t* Bb   = Ab + 2 * BM * HST;
    const int tid = threadIdx.x;
    const int lane = tid & 31, wid = tid >> 5;
    const int wm = (wid & 3) * 32, wn = (wid >> 2) * 64;
    ACC_INIT();
    LDSM_OFFSETS();
    const uint32_t sA = (uint32_t)__cvta_generic_to_shared(Ab) + aoff;
    const uint32_t sB = (uint32_t)__cvta_generic_to_shared(Bb) + boff;
    const int m0 = blockIdx.y * BM;
    const int n0 = blockIdx.x * BN;
    if (tid < BM) rows[tid] = x[m0 + tid];
    __syncthreads();

    STAGE_H(Ab, 256, 128, g_embed_h + (size_t)rows[r] * DIM + hh);
    STAGE_H(Bb, 256, 128, g_qkvwT + (size_t)(n0 + r) * DIM + hh);
    CP_COMMIT();

    for (int c = 0; c < 16; c++) {
        const int bf = c & 1;
        CP_WAIT0();
        __syncthreads();
        if (c + 1 < 16) {
            const int k1 = (c + 1) * BK;
            uint32_t* An = Ab + (bf ^ 1) * BM * HST;
            uint32_t* Bn = Bb + (bf ^ 1) * BM * HST;
            STAGE_H(An, 256, 128, g_embed_h + (size_t)rows[r] * DIM + k1 + hh);
            STAGE_H(Bn, 256, 128, g_qkvwT + (size_t)(n0 + r) * DIM + k1 + hh);
            CP_COMMIT();
        }
        TILE_LDSM(sA + bf * (BM * HST * 4), sB + bf * (BM * HST * 4));
    }
    const int g = lane >> 2, t = lane & 3;
    #pragma unroll
    for (int mi = 0; mi < 2; mi++)
        #pragma unroll
        for (int ni = 0; ni < 8; ni++) {
            int r0 = m0 + wm + mi * 16 + g;
            int c  = n0 + wn + ni * 8 + t * 2;
            float b0 = bias[c], b1 = bias[c + 1];
            float v0 = acc[mi][ni][0] + b0, v1 = acc[mi][ni][1] + b1;
            float v2 = acc[mi][ni][2] + b0, v3 = acc[mi][ni][3] + b1;
            if (n0 < QKW) {
                *(__half2*)(g_qkvh + (size_t)r0 * QKW + c) =
                    __floats2half2_rn(v0, v1);
                *(__half2*)(g_qkvh + (size_t)(r0 + 8) * QKW + c) =
                    __floats2half2_rn(v2, v3);
            } else {
                int d = c - QKW, bb = r0 >> 11, s = r0 & (SEQ - 1);
                __half* base = g_vT + (size_t)bb * DIM * SEQ;
                base[(size_t)d * SEQ + s]           = __float2half_rn(v0);
                base[(size_t)(d + 1) * SEQ + s]     = __float2half_rn(v1);
                base[(size_t)d * SEQ + s + 8]       = __float2half_rn(v2);
                base[(size_t)(d + 1) * SEQ + s + 8] = __float2half_rn(v3);
            }
        }
}

// ---------------------------------------------------------------------------
// 2) scores = Q @ K^T * scale  (lower-triangular blocks only)
// ---------------------------------------------------------------------------
__global__ __launch_bounds__(256, 2)
void scores_kernel()
{
    if (blockIdx.x > blockIdx.y) return;
    extern __shared__ uint32_t sm[];
    uint32_t* Ab = sm;
    uint32_t* Bb = Ab + 2 * BM * HST;
    const int tid = threadIdx.x;
    const int lane = tid & 31, wid = tid >> 5;
    const int wm = (wid & 3) * 32, wn = (wid >> 2) * 64;
    ACC_INIT();
    LDSM_OFFSETS();
    const uint32_t sA = (uint32_t)__cvta_generic_to_shared(Ab) + aoff;
    const uint32_t sB = (uint32_t)__cvta_generic_to_shared(Bb) + boff;
    const int b  = blockIdx.z;
    const int q0 = blockIdx.y * BM;
    const int n0 = blockIdx.x * BN;
    const __half* Q = g_qkvh + (size_t)(b * SEQ) * QKW;
    const __half* K = Q + DIM;

    STAGE_H(Ab, 256, 128, Q + (size_t)(q0 + r) * QKW + hh);
    STAGE_H(Bb, 256, 128, K + (size_t)(n0 + r) * QKW + hh);
    CP_COMMIT();

    for (int c = 0; c < 16; c++) {
        const int bf = c & 1;
        CP_WAIT0();
        __syncthreads();
        if (c + 1 < 16) {
            const int k1 = (c + 1) * BK;
            uint32_t* An = Ab + (bf ^ 1) * BM * HST;
            uint32_t* Bn = Bb + (bf ^ 1) * BM * HST;
            STAGE_H(An, 256, 128, Q + (size_t)(q0 + r) * QKW + k1 + hh);
            STAGE_H(Bn, 256, 128, K + (size_t)(n0 + r) * QKW + k1 + hh);
            CP_COMMIT();
        }
        TILE_LDSM(sA + bf * (BM * HST * 4), sB + bf * (BM * HST * 4));
    }
    const int g = lane >> 2, t = lane & 3;
    const float scale = 0.044194173824159216f;
    #pragma unroll
    for (int mi = 0; mi < 2; mi++)
        #pragma unroll
        for (int ni = 0; ni < 8; ni++) {
            int r0 = q0 + wm + mi * 16 + g;
            int c  = n0 + wn + ni * 8 + t * 2;
            float* p0 = g_scores + (size_t)(b * SEQ + r0) * SEQ + c;
            float* p1 = p0 + (size_t)8 * SEQ;
            *(float2*)p0 = make_float2(acc[mi][ni][0] * scale, acc[mi][ni][1] * scale);
            *(float2*)p1 = make_float2(acc[mi][ni][2] * scale, acc[mi][ni][3] * scale);
        }
}

// ---------------------------------------------------------------------------
// 3) causal softmax: fp32 scores -> fp16 attn; zero [L, kend)
// ---------------------------------------------------------------------------
__global__ __launch_bounds__(256)
void softmax_kernel()
{
    const int row = blockIdx.x;
    const int q = row & (SEQ - 1);
    const float* p = g_scores + (size_t)row * SEQ;
    __half* pa = g_attn + (size_t)row * SEQ;
    const int L = q + 1;
    const int kend = (q & ~127) + 128;
    const int tid = threadIdx.x;
    const int lane = tid & 31, wid = tid >> 5;
    __shared__ float red[8];
    __shared__ float ebuf[SEQ];

    float m = -1e30f;
    for (int k = tid; k < L; k += 256) {
        float v = p[k];
        ebuf[k] = v;
        m = fmaxf(m, v);
    }
    #pragma unroll
    for (int s = 16; s > 0; s >>= 1) m = fmaxf(m, __shfl_xor_sync(~0u, m, s));
    if (lane == 0) red[wid] = m;
    __syncthreads();
    m = red[lane & 7];
    #pragma unroll
    for (int s = 4; s > 0; s >>= 1) m = fmaxf(m, __shfl_xor_sync(~0u, m, s));

    float sum = 0.f;
    for (int k = tid; k < L; k += 256) {
        float e = __expf(ebuf[k] - m);
        ebuf[k] = e;
        sum += e;
    }
    #pragma unroll
    for (int s = 16; s > 0; s >>= 1) sum += __shfl_xor_sync(~0u, sum, s);
    __syncthreads();
    if (lane == 0) red[wid] = sum;
    __syncthreads();
    sum = red[lane & 7];
    #pragma unroll
    for (int s = 4; s > 0; s >>= 1) sum += __shfl_xor_sync(~0u, sum, s);

    const float inv = 1.0f / sum;
    for (int k = tid; k < L; k += 256) pa[k] = __float2half_rn(ebuf[k] * inv);
    for (int k = L + tid; k < kend; k += 256) pa[k] = __half(0.f);
}

// ---------------------------------------------------------------------------
// 4) out = attn @ V  (B = V^T n-major; k truncated at causal boundary)
// ---------------------------------------------------------------------------
__global__ __launch_bounds__(256, 2)
void attnv_kernel()
{
    extern __shared__ uint32_t sm[];
    uint32_t* Ab = sm;
    uint32_t* Bb = Ab + 2 * BM * HST;
    const int tid = threadIdx.x;
    const int lane = tid & 31, wid = tid >> 5;
    const int wm = (wid & 3) * 32, wn = (wid >> 2) * 64;
    ACC_INIT();
    LDSM_OFFSETS();
    const uint32_t sA = (uint32_t)__cvta_generic_to_shared(Ab) + aoff;
    const uint32_t sB = (uint32_t)__cvta_generic_to_shared(Bb) + boff;
    const int b  = blockIdx.z;
    const int q0 = blockIdx.y * BM;
    const int n0 = blockIdx.x * BN;
    const __half* A  = g_attn + (size_t)(b * SEQ) * SEQ;
    const __half* VT = g_vT + ((size_t)b * DIM + n0) * SEQ;

    STAGE_H(Ab, 256, 128, A + (size_t)(q0 + r) * SEQ + hh);
    STAGE_H(Bb, 256, 128, VT + (size_t)r * SEQ + hh);
    CP_COMMIT();

    const int NC = (q0 + BM) / BK;
    for (int c = 0; c < NC; c++) {
        const int bf = c & 1;
        CP_WAIT0();
        __syncthreads();
        if (c + 1 < NC) {
            const int k1 = (c + 1) * BK;
            uint32_t* An = Ab + (bf ^ 1) * BM * HST;
            uint32_t* Bn = Bb + (bf ^ 1) * BM * HST;
            STAGE_H(An, 256, 128, A + (size_t)(q0 + r) * SEQ + k1 + hh);
            STAGE_H(Bn, 256, 128, VT + (size_t)r * SEQ + k1 + hh);
            CP_COMMIT();
        }
        TILE_LDSM(sA + bf * (BM * HST * 4), sB + bf * (BM * HST * 4));
    }
    const int g = lane >> 2, t = lane & 3;
    #pragma unroll
    for (int mi = 0; mi < 2; mi++)
        #pragma unroll
        for (int ni = 0; ni < 8; ni++) {
            int r0 = q0 + wm + mi * 16 + g;
            int c  = n0 + wn + ni * 8 + t * 2;
            __half* base = g_attn_out + (size_t)(b * SEQ) * DIM;
            *(__half2*)(base + (size_t)r0 * DIM + c) =
                __floats2half2_rn(acc[mi][ni][0], acc[mi][ni][1]);
            *(__half2*)(base + (size_t)(r0 + 8) * DIM + c) =
                __floats2half2_rn(acc[mi][ni][2], acc[mi][ni][3]);
        }
}

// ---------------------------------------------------------------------------
// 5) logits = attn_out @ fc_w^T + fc_b   256x128 tile, 512 threads
// ---------------------------------------------------------------------------
#define LBM 256
__global__ __launch_bounds__(512, 1)
void logits_kernel(const float* __restrict__ bias, float* __restrict__ out)
{
    extern __shared__ uint32_t sm[];
    uint32_t* Ab = sm;
    uint32_t* Bb = Ab + 2 * LBM * HST;
    const int tid = threadIdx.x;
    const int lane = tid & 31, wid = tid >> 5;
    const int wm = (wid & 7) * 32, wn = (wid >> 3) * 64;
    ACC_INIT();
    LDSM_OFFSETS();
    const uint32_t sA = (uint32_t)__cvta_generic_to_shared(Ab) + aoff;
    const uint32_t sB = (uint32_t)__cvta_generic_to_shared(Bb) + boff;
    const int m0 = blockIdx.y * LBM;
    const int n0 = blockIdx.x * BN;

    STAGE_H(Ab, 512, 256, g_attn_out + (size_t)(m0 + r) * DIM + hh);
    STAGE_H(Bb, 512, 128, g_fcwT + (size_t)(n0 + r) * DIM + hh);
    CP_COMMIT();

    for (int c = 0; c < 16; c++) {
        const int bf = c & 1;
        CP_WAIT0();
        __syncthreads();
        if (c + 1 < 16) {
            const int k1 = (c + 1) * BK;
            uint32_t* An = Ab + (bf ^ 1) * LBM * HST;
            uint32_t* Bn = Bb + (bf ^ 1) * BM * HST;
            STAGE_H(An, 512, 256, g_attn_out + (size_t)(m0 + r) * DIM + k1 + hh);
            STAGE_H(Bn, 512, 128, g_fcwT + (size_t)(n0 + r) * DIM + k1 + hh);
            CP_COMMIT();
        }
        TILE_LDSM(sA + bf * (LBM * HST * 4), sB + bf * (BM * HST * 4));
    }
    const int g = lane >> 2, t = lane & 3;
    #pragma unroll
    for (int mi = 0; mi < 2; mi++)
        #pragma unroll
        for (int ni = 0; ni < 8; ni++) {
            int r0 = m0 + wm + mi * 16 + g;
            int c  = n0 + wn + ni * 8 + t * 2;
            float b0 = bias[c], b1 = bias[c + 1];
            float* p0 = out + (size_t)r0 * VOCAB + c;
            float* p1 = out + (size_t)(r0 + 8) * VOCAB + c;
            *(float2*)p0 = make_float2(acc[mi][ni][0] + b0, acc[mi][ni][1] + b1);
            *(float2*)p1 = make_float2(acc[mi][ni][2] + b0, acc[mi][ni][3] + b1);
        }
}

// ---------------------------------------------------------------------------
extern "C" void kernel_launch(void* const* d_in, const int* in_sizes, int n_in,
                              void* d_out, int out_size)
{
    (void)in_sizes; (void)n_in; (void)out_size;
    const int*   x     = (const int*)  d_in[0];
    const float* embed = (const float*)d_in[1];
    const float* qkv_w = (const float*)d_in[2];
    const float* qkv_b = (const float*)d_in[3];
    const float* fc_w  = (const float*)d_in[4];
    const float* fc_b  = (const float*)d_in[5];
    float* out = (float*)d_out;

    const int smem_qkv    = (128 + 4 * BM * HST) * 4;
    const int smem_scores = (4 * BM * HST) * 4;
    const int smem_attnv  = (4 * BM * HST) * 4;
    const int smem_logits = (2 * LBM * HST + 2 * BM * HST) * 4;

    cudaFuncSetAttribute(qkv_kernel,
        cudaFuncAttributeMaxDynamicSharedMemorySize, smem_qkv);
    cudaFuncSetAttribute(scores_kernel,
        cudaFuncAttributeMaxDynamicSharedMemorySize, smem_scores);
    cudaFuncSetAttribute(attnv_kernel,
        cudaFuncAttributeMaxDynamicSharedMemorySize, smem_attnv);
    cudaFuncSetAttribute(logits_kernel,
        cudaFuncAttributeMaxDynamicSharedMemorySize, smem_logits);

    __half* emb_dst;  cudaGetSymbolAddress((void**)&emb_dst,  g_embed_h);
    __half* qkvw_dst; cudaGetSymbolAddress((void**)&qkvw_dst, g_qkvwT);
    __half* fcw_dst;  cudaGetSymbolAddress((void**)&fcw_dst,  g_fcwT);

    cvt_half_kernel<<<VOCAB * DIM / 4 / 256, 256>>>(embed, emb_dst,
                                                    VOCAB * DIM / 4);
    transpose_cvt_kernel<<<dim3(NQKV / 32, DIM / 32), 256>>>(qkv_w, qkvw_dst, NQKV);
    transpose_cvt_kernel<<<dim3(VOCAB / 32, DIM / 32), 256>>>(fc_w, fcw_dst, VOCAB);

    qkv_kernel    <<<dim3(NQKV / BN, MTOK / BM), 256, smem_qkv>>>(x, qkv_b);
    scores_kernel <<<dim3(SEQ / BN, SEQ / BM, BATCH), 256, smem_scores>>>();
    softmax_kernel<<<MTOK, 256>>>();
    attnv_kernel  <<<dim3(DIM / BN, SEQ / BM, BATCH), 256, smem_attnv>>>();
    logits_kernel <<<dim3(VOCAB / BN, MTOK / LBM), 512, smem_logits>>>(fc_b, out);
}

// round 14
// speedup vs baseline: 2.4362x; 1.0972x over previous
#include <cuda_runtime.h>
#include <cuda_fp16.h>
#include <cstdint>
#include <cstddef>

// ---------------------------------------------------------------------------
// TinyTransformer B=4 S=2048 D=512 V=32000 — fp16 mma.sync m16n8k16 (f32 acc)
// R13: BK=64 chunks (8 per GEMM instead of 16) to amortize per-chunk
// sync/wait fixed costs. ldmatrix fragment loads, HST=36 stride (==4 mod 32,
// conflict-free). R7 wait0 double-buffer loop.
// ---------------------------------------------------------------------------

#define BATCH 4
#define SEQ   2048
#define DIM   512
#define VOCAB 32000
#define NQKV  1536
#define MTOK  8192
#define QKW   1024

#define BM 128
#define BN 128
#define BK 64                // 64 halves per chunk (128 B/row)
#define HST 36               // smem row stride in 32-bit words (32 data + 4 pad)

__device__ __align__(256) __half g_qkvh[(size_t)MTOK * QKW];
__device__ __align__(256) __half g_vT[(size_t)BATCH * DIM * SEQ];
__device__ float  g_scores[(size_t)BATCH * SEQ * SEQ];
__device__ __align__(256) __half g_attn[(size_t)BATCH * SEQ * SEQ];
__device__ __align__(256) __half g_attn_out[(size_t)MTOK * DIM];
__device__ __align__(256) __half g_embed_h[(size_t)VOCAB * DIM];
__device__ __align__(256) __half g_qkvwT[(size_t)NQKV * DIM];
__device__ __align__(256) __half g_fcwT[(size_t)VOCAB * DIM];

__device__ __forceinline__ void cpa16(void* s, const void* g) {
    uint32_t sa = (uint32_t)__cvta_generic_to_shared(s);
    asm volatile("cp.async.cg.shared.global [%0], [%1], 16;" :: "r"(sa), "l"(g));
}
#define CP_COMMIT() asm volatile("cp.async.commit_group;")
#define CP_WAIT0()  asm volatile("cp.async.wait_group 0;")

#define MMA_F16(c, a, b0, b1)                                                  \
    asm volatile(                                                              \
        "mma.sync.aligned.m16n8k16.row.col.f32.f16.f16.f32 "                   \
        "{%0,%1,%2,%3},{%4,%5,%6,%7},{%8,%9},{%0,%1,%2,%3};"                   \
        : "+f"(c[0]), "+f"(c[1]), "+f"(c[2]), "+f"(c[3])                       \
        : "r"(a[0]), "r"(a[1]), "r"(a[2]), "r"(a[3]), "r"(b0), "r"(b1));

#define LDSM4(r, addr)                                                         \
    asm volatile("ldmatrix.sync.aligned.m8n8.x4.shared.b16 {%0,%1,%2,%3}, [%4];" \
        : "=r"((r)[0]), "=r"((r)[1]), "=r"((r)[2]), "=r"((r)[3]) : "r"(addr))

#define ACC_INIT()                                                             \
    float acc[2][8][4];                                                        \
    _Pragma("unroll")                                                          \
    for (int i = 0; i < 2; i++)                                                \
        _Pragma("unroll")                                                      \
        for (int j = 0; j < 8; j++)                                            \
            _Pragma("unroll")                                                  \
            for (int k = 0; k < 4; k++) acc[i][j][k] = 0.f;

// Per-lane ldmatrix address components (bytes, relative to tile base):
//   A: rows (wm + (l&7) + ((l>>3)&1)*8), k16-halfsel ((l>>4)&1) -> +16B
//   B: rows (wn + (l&7) + ((l>>4)&1)*8), k16-halfsel ((l>>3)&1) -> +16B
#define LDSM_OFFSETS()                                                         \
    const uint32_t aoff = (uint32_t)(((wm + (lane & 7) + ((lane >> 3) & 1) * 8) \
                         * HST + ((lane >> 4) & 1) * 4) * 4);                  \
    const uint32_t boff = (uint32_t)(((wn + (lane & 7) + ((lane >> 4) & 1) * 8) \
                         * HST + ((lane >> 3) & 1) * 4) * 4);

// One BK=64 chunk via ldmatrix: 4 k16 steps.
#define TILE_LDSM(aA, aB)                                                      \
    _Pragma("unroll")                                                          \
    for (int kk = 0; kk < 4; kk++) {                                           \
        uint32_t a0[4], a1[4];                                                 \
        LDSM4(a0, (aA) + kk * 32);                                             \
        LDSM4(a1, (aA) + 16 * HST * 4 + kk * 32);                              \
        _Pragma("unroll")                                                      \
        for (int p = 0; p < 4; p++) {                                          \
            uint32_t bb[4];                                                    \
            LDSM4(bb, (aB) + p * 16 * HST * 4 + kk * 32);                      \
            MMA_F16(acc[0][2 * p],     a0, bb[0], bb[1]);                      \
            MMA_F16(acc[1][2 * p],     a1, bb[0], bb[1]);                      \
            MMA_F16(acc[0][2 * p + 1], a0, bb[2], bb[3]);                      \
            MMA_F16(acc[1][2 * p + 1], a1, bb[2], bb[3]);                      \
        }                                                                      \
    }

// Stage ROWS x 64 halves (128 B/row = 8 x 16 B).
#define STAGE_H(DST, NT, ROWS, PTR_EXPR)                                       \
    _Pragma("unroll")                                                          \
    for (int i = 0; i < (ROWS * 8) / NT; i++) {                                \
        int v = tid + i * NT, r = v >> 3, hh = (v & 7) * 8;                    \
        cpa16((DST) + r * HST + (v & 7) * 4, PTR_EXPR);                        \
    }

// ---------------------------------------------------------------------------
// 0a) fp32 -> fp16 elementwise (embed)
// ---------------------------------------------------------------------------
__global__ __launch_bounds__(256)
void cvt_half_kernel(const float* __restrict__ src, __half* __restrict__ dst,
                     int n4)
{
    int i = blockIdx.x * 256 + threadIdx.x;
    if (i < n4) {
        float4 f = ((const float4*)src)[i];
        ((__half2*)dst)[i * 2]     = __floats2half2_rn(f.x, f.y);
        ((__half2*)dst)[i * 2 + 1] = __floats2half2_rn(f.z, f.w);
    }
}

// ---------------------------------------------------------------------------
// 0b) weights: transpose + cvt   src fp32 [DIM][ncols] -> dst fp16 [ncols][DIM]
// ---------------------------------------------------------------------------
__global__ __launch_bounds__(256)
void transpose_cvt_kernel(const float* __restrict__ src,
                          __half* __restrict__ dst, int ncols)
{
    __shared__ float tile[32][33];
    const int c0 = blockIdx.x * 32;
    const int r0 = blockIdx.y * 32;
    const int xx = threadIdx.x & 31, yy = threadIdx.x >> 5;
    #pragma unroll
    for (int i = 0; i < 32; i += 8)
        tile[yy + i][xx] = src[(size_t)(r0 + yy + i) * ncols + c0 + xx];
    __syncthreads();
    #pragma unroll
    for (int i = 0; i < 32; i += 8)
        dst[(size_t)(c0 + yy + i) * DIM + r0 + xx] =
            __float2half_rn(tile[xx][yy + i]);
}

// ---------------------------------------------------------------------------
// 1) qkv = gather(embed,x) @ qkv_w + b.  Q/K -> g_qkvh; V -> g_vT.
// ---------------------------------------------------------------------------
__global__ __launch_bounds__(256, 2)
void qkv_kernel(const int* __restrict__ x, const float* __restrict__ bias)
{
    extern __shared__ uint32_t sm[];
    int*      rows = (int*)sm;
    uint32_t* Ab   = sm + 128;
    uint32_t* Bb   = Ab + 2 * BM * HST;
    const int tid = threadIdx.x;
    const int lane = tid & 31, wid = tid >> 5;
    const int wm = (wid & 3) * 32, wn = (wid >> 2) * 64;
    ACC_INIT();
    LDSM_OFFSETS();
    const uint32_t sA = (uint32_t)__cvta_generic_to_shared(Ab) + aoff;
    const uint32_t sB = (uint32_t)__cvta_generic_to_shared(Bb) + boff;
    const int m0 = blockIdx.y * BM;
    const int n0 = blockIdx.x * BN;
    if (tid < BM) rows[tid] = x[m0 + tid];
    __syncthreads();

    STAGE_H(Ab, 256, 128, g_embed_h + (size_t)rows[r] * DIM + hh);
    STAGE_H(Bb, 256, 128, g_qkvwT + (size_t)(n0 + r) * DIM + hh);
    CP_COMMIT();

    for (int c = 0; c < 8; c++) {
        const int bf = c & 1;
        CP_WAIT0();
        __syncthreads();
        if (c + 1 < 8) {
            const int k1 = (c + 1) * BK;
            uint32_t* An = Ab + (bf ^ 1) * BM * HST;
            uint32_t* Bn = Bb + (bf ^ 1) * BM * HST;
            STAGE_H(An, 256, 128, g_embed_h + (size_t)rows[r] * DIM + k1 + hh);
            STAGE_H(Bn, 256, 128, g_qkvwT + (size_t)(n0 + r) * DIM + k1 + hh);
            CP_COMMIT();
        }
        TILE_LDSM(sA + bf * (BM * HST * 4), sB + bf * (BM * HST * 4));
    }
    const int g = lane >> 2, t = lane & 3;
    #pragma unroll
    for (int mi = 0; mi < 2; mi++)
        #pragma unroll
        for (int ni = 0; ni < 8; ni++) {
            int r0 = m0 + wm + mi * 16 + g;
            int c  = n0 + wn + ni * 8 + t * 2;
            float b0 = bias[c], b1 = bias[c + 1];
            float v0 = acc[mi][ni][0] + b0, v1 = acc[mi][ni][1] + b1;
            float v2 = acc[mi][ni][2] + b0, v3 = acc[mi][ni][3] + b1;
            if (n0 < QKW) {
                *(__half2*)(g_qkvh + (size_t)r0 * QKW + c) =
                    __floats2half2_rn(v0, v1);
                *(__half2*)(g_qkvh + (size_t)(r0 + 8) * QKW + c) =
                    __floats2half2_rn(v2, v3);
            } else {
                int d = c - QKW, bb = r0 >> 11, s = r0 & (SEQ - 1);
                __half* base = g_vT + (size_t)bb * DIM * SEQ;
                base[(size_t)d * SEQ + s]           = __float2half_rn(v0);
                base[(size_t)(d + 1) * SEQ + s]     = __float2half_rn(v1);
                base[(size_t)d * SEQ + s + 8]       = __float2half_rn(v2);
                base[(size_t)(d + 1) * SEQ + s + 8] = __float2half_rn(v3);
            }
        }
}

// ---------------------------------------------------------------------------
// 2) scores = Q @ K^T * scale  (lower-triangular blocks only)
// ---------------------------------------------------------------------------
__global__ __launch_bounds__(256, 2)
void scores_kernel()
{
    if (blockIdx.x > blockIdx.y) return;
    extern __shared__ uint32_t sm[];
    uint32_t* Ab = sm;
    uint32_t* Bb = Ab + 2 * BM * HST;
    const int tid = threadIdx.x;
    const int lane = tid & 31, wid = tid >> 5;
    const int wm = (wid & 3) * 32, wn = (wid >> 2) * 64;
    ACC_INIT();
    LDSM_OFFSETS();
    const uint32_t sA = (uint32_t)__cvta_generic_to_shared(Ab) + aoff;
    const uint32_t sB = (uint32_t)__cvta_generic_to_shared(Bb) + boff;
    const int b  = blockIdx.z;
    const int q0 = blockIdx.y * BM;
    const int n0 = blockIdx.x * BN;
    const __half* Q = g_qkvh + (size_t)(b * SEQ) * QKW;
    const __half* K = Q + DIM;

    STAGE_H(Ab, 256, 128, Q + (size_t)(q0 + r) * QKW + hh);
    STAGE_H(Bb, 256, 128, K + (size_t)(n0 + r) * QKW + hh);
    CP_COMMIT();

    for (int c = 0; c < 8; c++) {
        const int bf = c & 1;
        CP_WAIT0();
        __syncthreads();
        if (c + 1 < 8) {
            const int k1 = (c + 1) * BK;
            uint32_t* An = Ab + (bf ^ 1) * BM * HST;
            uint32_t* Bn = Bb + (bf ^ 1) * BM * HST;
            STAGE_H(An, 256, 128, Q + (size_t)(q0 + r) * QKW + k1 + hh);
            STAGE_H(Bn, 256, 128, K + (size_t)(n0 + r) * QKW + k1 + hh);
            CP_COMMIT();
        }
        TILE_LDSM(sA + bf * (BM * HST * 4), sB + bf * (BM * HST * 4));
    }
    const int g = lane >> 2, t = lane & 3;
    const float scale = 0.044194173824159216f;
    #pragma unroll
    for (int mi = 0; mi < 2; mi++)
        #pragma unroll
        for (int ni = 0; ni < 8; ni++) {
            int r0 = q0 + wm + mi * 16 + g;
            int c  = n0 + wn + ni * 8 + t * 2;
            float* p0 = g_scores + (size_t)(b * SEQ + r0) * SEQ + c;
            float* p1 = p0 + (size_t)8 * SEQ;
            *(float2*)p0 = make_float2(acc[mi][ni][0] * scale, acc[mi][ni][1] * scale);
            *(float2*)p1 = make_float2(acc[mi][ni][2] * scale, acc[mi][ni][3] * scale);
        }
}

// ---------------------------------------------------------------------------
// 3) causal softmax: fp32 scores -> fp16 attn; zero [L, kend)
// ---------------------------------------------------------------------------
__global__ __launch_bounds__(256)
void softmax_kernel()
{
    const int row = blockIdx.x;
    const int q = row & (SEQ - 1);
    const float* p = g_scores + (size_t)row * SEQ;
    __half* pa = g_attn + (size_t)row * SEQ;
    const int L = q + 1;
    const int kend = (q & ~127) + 128;
    const int tid = threadIdx.x;
    const int lane = tid & 31, wid = tid >> 5;
    __shared__ float red[8];
    __shared__ float ebuf[SEQ];

    float m = -1e30f;
    for (int k = tid; k < L; k += 256) {
        float v = p[k];
        ebuf[k] = v;
        m = fmaxf(m, v);
    }
    #pragma unroll
    for (int s = 16; s > 0; s >>= 1) m = fmaxf(m, __shfl_xor_sync(~0u, m, s));
    if (lane == 0) red[wid] = m;
    __syncthreads();
    m = red[lane & 7];
    #pragma unroll
    for (int s = 4; s > 0; s >>= 1) m = fmaxf(m, __shfl_xor_sync(~0u, m, s));

    float sum = 0.f;
    for (int k = tid; k < L; k += 256) {
        float e = __expf(ebuf[k] - m);
        ebuf[k] = e;
        sum += e;
    }
    #pragma unroll
    for (int s = 16; s > 0; s >>= 1) sum += __shfl_xor_sync(~0u, sum, s);
    __syncthreads();
    if (lane == 0) red[wid] = sum;
    __syncthreads();
    sum = red[lane & 7];
    #pragma unroll
    for (int s = 4; s > 0; s >>= 1) sum += __shfl_xor_sync(~0u, sum, s);

    const float inv = 1.0f / sum;
    for (int k = tid; k < L; k += 256) pa[k] = __float2half_rn(ebuf[k] * inv);
    for (int k = L + tid; k < kend; k += 256) pa[k] = __half(0.f);
}

// ---------------------------------------------------------------------------
// 4) out = attn @ V  (B = V^T n-major; k truncated at causal boundary)
// ---------------------------------------------------------------------------
__global__ __launch_bounds__(256, 2)
void attnv_kernel()
{
    extern __shared__ uint32_t sm[];
    uint32_t* Ab = sm;
    uint32_t* Bb = Ab + 2 * BM * HST;
    const int tid = threadIdx.x;
    const int lane = tid & 31, wid = tid >> 5;
    const int wm = (wid & 3) * 32, wn = (wid >> 2) * 64;
    ACC_INIT();
    LDSM_OFFSETS();
    const uint32_t sA = (uint32_t)__cvta_generic_to_shared(Ab) + aoff;
    const uint32_t sB = (uint32_t)__cvta_generic_to_shared(Bb) + boff;
    const int b  = blockIdx.z;
    const int q0 = blockIdx.y * BM;
    const int n0 = blockIdx.x * BN;
    const __half* A  = g_attn + (size_t)(b * SEQ) * SEQ;
    const __half* VT = g_vT + ((size_t)b * DIM + n0) * SEQ;

    STAGE_H(Ab, 256, 128, A + (size_t)(q0 + r) * SEQ + hh);
    STAGE_H(Bb, 256, 128, VT + (size_t)r * SEQ + hh);
    CP_COMMIT();

    const int NC = (q0 + BM) / BK;
    for (int c = 0; c < NC; c++) {
        const int bf = c & 1;
        CP_WAIT0();
        __syncthreads();
        if (c + 1 < NC) {
            const int k1 = (c + 1) * BK;
            uint32_t* An = Ab + (bf ^ 1) * BM * HST;
            uint32_t* Bn = Bb + (bf ^ 1) * BM * HST;
            STAGE_H(An, 256, 128, A + (size_t)(q0 + r) * SEQ + k1 + hh);
            STAGE_H(Bn, 256, 128, VT + (size_t)r * SEQ + k1 + hh);
            CP_COMMIT();
        }
        TILE_LDSM(sA + bf * (BM * HST * 4), sB + bf * (BM * HST * 4));
    }
    const int g = lane >> 2, t = lane & 3;
    #pragma unroll
    for (int mi = 0; mi < 2; mi++)
        #pragma unroll
        for (int ni = 0; ni < 8; ni++) {
            int r0 = q0 + wm + mi * 16 + g;
            int c  = n0 + wn + ni * 8 + t * 2;
            __half* base = g_attn_out + (size_t)(b * SEQ) * DIM;
            *(__half2*)(base + (size_t)r0 * DIM + c) =
                __floats2half2_rn(acc[mi][ni][0], acc[mi][ni][1]);
            *(__half2*)(base + (size_t)(r0 + 8) * DIM + c) =
                __floats2half2_rn(acc[mi][ni][2], acc[mi][ni][3]);
        }
}

// ---------------------------------------------------------------------------
// 5) logits = attn_out @ fc_w^T + fc_b   256x128 tile, 512 threads
// ---------------------------------------------------------------------------
#define LBM 256
__global__ __launch_bounds__(512, 1)
void logits_kernel(const float* __restrict__ bias, float* __restrict__ out)
{
    extern __shared__ uint32_t sm[];
    uint32_t* Ab = sm;
    uint32_t* Bb = Ab + 2 * LBM * HST;
    const int tid = threadIdx.x;
    const int lane = tid & 31, wid = tid >> 5;
    const int wm = (wid & 7) * 32, wn = (wid >> 3) * 64;
    ACC_INIT();
    LDSM_OFFSETS();
    const uint32_t sA = (uint32_t)__cvta_generic_to_shared(Ab) + aoff;
    const uint32_t sB = (uint32_t)__cvta_generic_to_shared(Bb) + boff;
    const int m0 = blockIdx.y * LBM;
    const int n0 = blockIdx.x * BN;

    STAGE_H(Ab, 512, 256, g_attn_out + (size_t)(m0 + r) * DIM + hh);
    STAGE_H(Bb, 512, 128, g_fcwT + (size_t)(n0 + r) * DIM + hh);
    CP_COMMIT();

    for (int c = 0; c < 8; c++) {
        const int bf = c & 1;
        CP_WAIT0();
        __syncthreads();
        if (c + 1 < 8) {
            const int k1 = (c + 1) * BK;
            uint32_t* An = Ab + (bf ^ 1) * LBM * HST;
            uint32_t* Bn = Bb + (bf ^ 1) * BM * HST;
            STAGE_H(An, 512, 256, g_attn_out + (size_t)(m0 + r) * DIM + k1 + hh);
            STAGE_H(Bn, 512, 128, g_fcwT + (size_t)(n0 + r) * DIM + k1 + hh);
            CP_COMMIT();
        }
        TILE_LDSM(sA + bf * (LBM * HST * 4), sB + bf * (BM * HST * 4));
    }
    const int g = lane >> 2, t = lane & 3;
    #pragma unroll
    for (int mi = 0; mi < 2; mi++)
        #pragma unroll
        for (int ni = 0; ni < 8; ni++) {
            int r0 = m0 + wm + mi * 16 + g;
            int c  = n0 + wn + ni * 8 + t * 2;
            float b0 = bias[c], b1 = bias[c + 1];
            float* p0 = out + (size_t)r0 * VOCAB + c;
            float* p1 = out + (size_t)(r0 + 8) * VOCAB + c;
            *(float2*)p0 = make_float2(acc[mi][ni][0] + b0, acc[mi][ni][1] + b1);
            *(float2*)p1 = make_float2(acc[mi][ni][2] + b0, acc[mi][ni][3] + b1);
        }
}

// ---------------------------------------------------------------------------
extern "C" void kernel_launch(void* const* d_in, const int* in_sizes, int n_in,
                              void* d_out, int out_size)
{
    (void)in_sizes; (void)n_in; (void)out_size;
    const int*   x     = (const int*)  d_in[0];
    const float* embed = (const float*)d_in[1];
    const float* qkv_w = (const float*)d_in[2];
    const float* qkv_b = (const float*)d_in[3];
    const float* fc_w  = (const float*)d_in[4];
    const float* fc_b  = (const float*)d_in[5];
    float* out = (float*)d_out;

    const int smem_qkv    = (128 + 4 * BM * HST) * 4;            // ~74.2 KB
    const int smem_scores = (4 * BM * HST) * 4;                  // ~73.7 KB
    const int smem_attnv  = (4 * BM * HST) * 4;                  // ~73.7 KB
    const int smem_logits = (2 * LBM * HST + 2 * BM * HST) * 4;  // ~110.6 KB

    cudaFuncSetAttribute(qkv_kernel,
        cudaFuncAttributeMaxDynamicSharedMemorySize, smem_qkv);
    cudaFuncSetAttribute(scores_kernel,
        cudaFuncAttributeMaxDynamicSharedMemorySize, smem_scores);
    cudaFuncSetAttribute(attnv_kernel,
        cudaFuncAttributeMaxDynamicSharedMemorySize, smem_attnv);
    cudaFuncSetAttribute(logits_kernel,
        cudaFuncAttributeMaxDynamicSharedMemorySize, smem_logits);

    __half* emb_dst;  cudaGetSymbolAddress((void**)&emb_dst,  g_embed_h);
    __half* qkvw_dst; cudaGetSymbolAddress((void**)&qkvw_dst, g_qkvwT);
    __half* fcw_dst;  cudaGetSymbolAddress((void**)&fcw_dst,  g_fcwT);

    cvt_half_kernel<<<VOCAB * DIM / 4 / 256, 256>>>(embed, emb_dst,
                                                    VOCAB * DIM / 4);
    transpose_cvt_kernel<<<dim3(NQKV / 32, DIM / 32), 256>>>(qkv_w, qkvw_dst, NQKV);
    transpose_cvt_kernel<<<dim3(VOCAB / 32, DIM / 32), 256>>>(fc_w, fcw_dst, VOCAB);

    qkv_kernel    <<<dim3(NQKV / BN, MTOK / BM), 256, smem_qkv>>>(x, qkv_b);
    scores_kernel <<<dim3(SEQ / BN, SEQ / BM, BATCH), 256, smem_scores>>>();
    softmax_kernel<<<MTOK, 256>>>();
    attnv_kernel  <<<dim3(DIM / BN, SEQ / BM, BATCH), 256, smem_attnv>>>();
    logits_kernel <<<dim3(VOCAB / BN, MTOK / LBM), 512, smem_logits>>>(fc_b, out);
}

// round 15
// speedup vs baseline: 2.6607x; 1.0921x over previous
#include <cuda_runtime.h>
#include <cuda_fp16.h>
#include <cstdint>
#include <cstddef>

// ---------------------------------------------------------------------------
// TinyTransformer B=4 S=2048 D=512 V=32000 — fp16 mma.sync m16n8k16 (f32 acc)
// R14: (1) B-fragment software rotation inside TILE_LDSM — the LDSM for
// sub-tile p+1 issues before the MMAs of p, hiding ldmatrix latency;
// (2) logits uses a 3-stage cp.async ring (wait_group 1).
// BK=64, HST=36 (==4 mod 32, conflict-free), ldmatrix fragment loads.
// ---------------------------------------------------------------------------

#define BATCH 4
#define SEQ   2048
#define DIM   512
#define VOCAB 32000
#define NQKV  1536
#define MTOK  8192
#define QKW   1024

#define BM 128
#define BN 128
#define BK 64                // 64 halves per chunk (128 B/row)
#define HST 36               // smem row stride in 32-bit words

__device__ __align__(256) __half g_qkvh[(size_t)MTOK * QKW];
__device__ __align__(256) __half g_vT[(size_t)BATCH * DIM * SEQ];
__device__ float  g_scores[(size_t)BATCH * SEQ * SEQ];
__device__ __align__(256) __half g_attn[(size_t)BATCH * SEQ * SEQ];
__device__ __align__(256) __half g_attn_out[(size_t)MTOK * DIM];
__device__ __align__(256) __half g_embed_h[(size_t)VOCAB * DIM];
__device__ __align__(256) __half g_qkvwT[(size_t)NQKV * DIM];
__device__ __align__(256) __half g_fcwT[(size_t)VOCAB * DIM];

__device__ __forceinline__ void cpa16(void* s, const void* g) {
    uint32_t sa = (uint32_t)__cvta_generic_to_shared(s);
    asm volatile("cp.async.cg.shared.global [%0], [%1], 16;" :: "r"(sa), "l"(g));
}
#define CP_COMMIT() asm volatile("cp.async.commit_group;")
#define CP_WAIT0()  asm volatile("cp.async.wait_group 0;")
#define CP_WAIT1()  asm volatile("cp.async.wait_group 1;")

#define MMA_F16(c, a, b0, b1)                                                  \
    asm volatile(                                                              \
        "mma.sync.aligned.m16n8k16.row.col.f32.f16.f16.f32 "                   \
        "{%0,%1,%2,%3},{%4,%5,%6,%7},{%8,%9},{%0,%1,%2,%3};"                   \
        : "+f"(c[0]), "+f"(c[1]), "+f"(c[2]), "+f"(c[3])                       \
        : "r"(a[0]), "r"(a[1]), "r"(a[2]), "r"(a[3]), "r"(b0), "r"(b1));

#define LDSM4(r, addr)                                                         \
    asm volatile("ldmatrix.sync.aligned.m8n8.x4.shared.b16 {%0,%1,%2,%3}, [%4];" \
        : "=r"((r)[0]), "=r"((r)[1]), "=r"((r)[2]), "=r"((r)[3]) : "r"(addr))

#define ACC_INIT()                                                             \
    float acc[2][8][4];                                                        \
    _Pragma("unroll")                                                          \
    for (int i = 0; i < 2; i++)                                                \
        _Pragma("unroll")                                                      \
        for (int j = 0; j < 8; j++)                                            \
            _Pragma("unroll")                                                  \
            for (int k = 0; k < 4; k++) acc[i][j][k] = 0.f;

#define LDSM_OFFSETS()                                                         \
    const uint32_t aoff = (uint32_t)(((wm + (lane & 7) + ((lane >> 3) & 1) * 8) \
                         * HST + ((lane >> 4) & 1) * 4) * 4);                  \
    const uint32_t boff = (uint32_t)(((wn + (lane & 7) + ((lane >> 4) & 1) * 8) \
                         * HST + ((lane >> 3) & 1) * 4) * 4);

// One BK=64 chunk. B fragments rotate: LDSM for p+1 issues before MMAs of p.
#define TILE_LDSM(aA, aB)                                                      \
    _Pragma("unroll")                                                          \
    for (int kk = 0; kk < 4; kk++) {                                           \
        uint32_t a0[4], a1[4], bb0[4], bb1[4];                                 \
        LDSM4(a0, (aA) + kk * 32);                                             \
        LDSM4(a1, (aA) + 16 * HST * 4 + kk * 32);                              \
        LDSM4(bb0, (aB) + kk * 32);                                            \
        _Pragma("unroll")                                                      \
        for (int p = 0; p < 4; p++) {                                          \
            if (p < 3) LDSM4(bb1, (aB) + (p + 1) * 16 * HST * 4 + kk * 32);    \
            MMA_F16(acc[0][2 * p],     a0, bb0[0], bb0[1]);                    \
            MMA_F16(acc[1][2 * p],     a1, bb0[0], bb0[1]);                    \
            MMA_F16(acc[0][2 * p + 1], a0, bb0[2], bb0[3]);                    \
            MMA_F16(acc[1][2 * p + 1], a1, bb0[2], bb0[3]);                    \
            _Pragma("unroll")                                                  \
            for (int q_ = 0; q_ < 4; q_++) bb0[q_] = bb1[q_];                  \
        }                                                                      \
    }

// Stage ROWS x 64 halves (128 B/row = 8 x 16 B).
#define STAGE_H(DST, NT, ROWS, PTR_EXPR)                                       \
    _Pragma("unroll")                                                          \
    for (int i = 0; i < (ROWS * 8) / NT; i++) {                                \
        int v = tid + i * NT, r = v >> 3, hh = (v & 7) * 8;                    \
        cpa16((DST) + r * HST + (v & 7) * 4, PTR_EXPR);                        \
    }

// ---------------------------------------------------------------------------
// 0a) fp32 -> fp16 elementwise (embed)
// ---------------------------------------------------------------------------
__global__ __launch_bounds__(256)
void cvt_half_kernel(const float* __restrict__ src, __half* __restrict__ dst,
                     int n4)
{
    int i = blockIdx.x * 256 + threadIdx.x;
    if (i < n4) {
        float4 f = ((const float4*)src)[i];
        ((__half2*)dst)[i * 2]     = __floats2half2_rn(f.x, f.y);
        ((__half2*)dst)[i * 2 + 1] = __floats2half2_rn(f.z, f.w);
    }
}

// ---------------------------------------------------------------------------
// 0b) weights: transpose + cvt   src fp32 [DIM][ncols] -> dst fp16 [ncols][DIM]
// ---------------------------------------------------------------------------
__global__ __launch_bounds__(256)
void transpose_cvt_kernel(const float* __restrict__ src,
                          __half* __restrict__ dst, int ncols)
{
    __shared__ float tile[32][33];
    const int c0 = blockIdx.x * 32;
    const int r0 = blockIdx.y * 32;
    const int xx = threadIdx.x & 31, yy = threadIdx.x >> 5;
    #pragma unroll
    for (int i = 0; i < 32; i += 8)
        tile[yy + i][xx] = src[(size_t)(r0 + yy + i) * ncols + c0 + xx];
    __syncthreads();
    #pragma unroll
    for (int i = 0; i < 32; i += 8)
        dst[(size_t)(c0 + yy + i) * DIM + r0 + xx] =
            __float2half_rn(tile[xx][yy + i]);
}

// ---------------------------------------------------------------------------
// 1) qkv = gather(embed,x) @ qkv_w + b.  Q/K -> g_qkvh; V -> g_vT.
// ---------------------------------------------------------------------------
__global__ __launch_bounds__(256, 2)
void qkv_kernel(const int* __restrict__ x, const float* __restrict__ bias)
{
    extern __shared__ uint32_t sm[];
    int*      rows = (int*)sm;
    uint32_t* Ab   = sm + 128;
    uint32_t* Bb   = Ab + 2 * BM * HST;
    const int tid = threadIdx.x;
    const int lane = tid & 31, wid = tid >> 5;
    const int wm = (wid & 3) * 32, wn = (wid >> 2) * 64;
    ACC_INIT();
    LDSM_OFFSETS();
    const uint32_t sA = (uint32_t)__cvta_generic_to_shared(Ab) + aoff;
    const uint32_t sB = (uint32_t)__cvta_generic_to_shared(Bb) + boff;
    const int m0 = blockIdx.y * BM;
    const int n0 = blockIdx.x * BN;
    if (tid < BM) rows[tid] = x[m0 + tid];
    __syncthreads();

    STAGE_H(Ab, 256, 128, g_embed_h + (size_t)rows[r] * DIM + hh);
    STAGE_H(Bb, 256, 128, g_qkvwT + (size_t)(n0 + r) * DIM + hh);
    CP_COMMIT();

    for (int c = 0; c < 8; c++) {
        const int bf = c & 1;
        CP_WAIT0();
        __syncthreads();
        if (c + 1 < 8) {
            const int k1 = (c + 1) * BK;
            uint32_t* An = Ab + (bf ^ 1) * BM * HST;
            uint32_t* Bn = Bb + (bf ^ 1) * BM * HST;
            STAGE_H(An, 256, 128, g_embed_h + (size_t)rows[r] * DIM + k1 + hh);
            STAGE_H(Bn, 256, 128, g_qkvwT + (size_t)(n0 + r) * DIM + k1 + hh);
            CP_COMMIT();
        }
        TILE_LDSM(sA + bf * (BM * HST * 4), sB + bf * (BM * HST * 4));
    }
    const int g = lane >> 2, t = lane & 3;
    #pragma unroll
    for (int mi = 0; mi < 2; mi++)
        #pragma unroll
        for (int ni = 0; ni < 8; ni++) {
            int r0 = m0 + wm + mi * 16 + g;
            int c  = n0 + wn + ni * 8 + t * 2;
            float b0 = bias[c], b1 = bias[c + 1];
            float v0 = acc[mi][ni][0] + b0, v1 = acc[mi][ni][1] + b1;
            float v2 = acc[mi][ni][2] + b0, v3 = acc[mi][ni][3] + b1;
            if (n0 < QKW) {
                *(__half2*)(g_qkvh + (size_t)r0 * QKW + c) =
                    __floats2half2_rn(v0, v1);
                *(__half2*)(g_qkvh + (size_t)(r0 + 8) * QKW + c) =
                    __floats2half2_rn(v2, v3);
            } else {
                int d = c - QKW, bb = r0 >> 11, s = r0 & (SEQ - 1);
                __half* base = g_vT + (size_t)bb * DIM * SEQ;
                base[(size_t)d * SEQ + s]           = __float2half_rn(v0);
                base[(size_t)(d + 1) * SEQ + s]     = __float2half_rn(v1);
                base[(size_t)d * SEQ + s + 8]       = __float2half_rn(v2);
                base[(size_t)(d + 1) * SEQ + s + 8] = __float2half_rn(v3);
            }
        }
}

// ---------------------------------------------------------------------------
// 2) scores = Q @ K^T * scale  (lower-triangular blocks only)
// ---------------------------------------------------------------------------
__global__ __launch_bounds__(256, 2)
void scores_kernel()
{
    if (blockIdx.x > blockIdx.y) return;
    extern __shared__ uint32_t sm[];
    uint32_t* Ab = sm;
    uint32_t* Bb = Ab + 2 * BM * HST;
    const int tid = threadIdx.x;
    const int lane = tid & 31, wid = tid >> 5;
    const int wm = (wid & 3) * 32, wn = (wid >> 2) * 64;
    ACC_INIT();
    LDSM_OFFSETS();
    const uint32_t sA = (uint32_t)__cvta_generic_to_shared(Ab) + aoff;
    const uint32_t sB = (uint32_t)__cvta_generic_to_shared(Bb) + boff;
    const int b  = blockIdx.z;
    const int q0 = blockIdx.y * BM;
    const int n0 = blockIdx.x * BN;
    const __half* Q = g_qkvh + (size_t)(b * SEQ) * QKW;
    const __half* K = Q + DIM;

    STAGE_H(Ab, 256, 128, Q + (size_t)(q0 + r) * QKW + hh);
    STAGE_H(Bb, 256, 128, K + (size_t)(n0 + r) * QKW + hh);
    CP_COMMIT();

    for (int c = 0; c < 8; c++) {
        const int bf = c & 1;
        CP_WAIT0();
        __syncthreads();
        if (c + 1 < 8) {
            const int k1 = (c + 1) * BK;
            uint32_t* An = Ab + (bf ^ 1) * BM * HST;
            uint32_t* Bn = Bb + (bf ^ 1) * BM * HST;
            STAGE_H(An, 256, 128, Q + (size_t)(q0 + r) * QKW + k1 + hh);
            STAGE_H(Bn, 256, 128, K + (size_t)(n0 + r) * QKW + k1 + hh);
            CP_COMMIT();
        }
        TILE_LDSM(sA + bf * (BM * HST * 4), sB + bf * (BM * HST * 4));
    }
    const int g = lane >> 2, t = lane & 3;
    const float scale = 0.044194173824159216f;
    #pragma unroll
    for (int mi = 0; mi < 2; mi++)
        #pragma unroll
        for (int ni = 0; ni < 8; ni++) {
            int r0 = q0 + wm + mi * 16 + g;
            int c  = n0 + wn + ni * 8 + t * 2;
            float* p0 = g_scores + (size_t)(b * SEQ + r0) * SEQ + c;
            float* p1 = p0 + (size_t)8 * SEQ;
            *(float2*)p0 = make_float2(acc[mi][ni][0] * scale, acc[mi][ni][1] * scale);
            *(float2*)p1 = make_float2(acc[mi][ni][2] * scale, acc[mi][ni][3] * scale);
        }
}

// ---------------------------------------------------------------------------
// 3) causal softmax: fp32 scores -> fp16 attn; zero [L, kend)
// ---------------------------------------------------------------------------
__global__ __launch_bounds__(256)
void softmax_kernel()
{
    const int row = blockIdx.x;
    const int q = row & (SEQ - 1);
    const float* p = g_scores + (size_t)row * SEQ;
    __half* pa = g_attn + (size_t)row * SEQ;
    const int L = q + 1;
    const int kend = (q & ~127) + 128;
    const int tid = threadIdx.x;
    const int lane = tid & 31, wid = tid >> 5;
    __shared__ float red[8];
    __shared__ float ebuf[SEQ];

    float m = -1e30f;
    for (int k = tid; k < L; k += 256) {
        float v = p[k];
        ebuf[k] = v;
        m = fmaxf(m, v);
    }
    #pragma unroll
    for (int s = 16; s > 0; s >>= 1) m = fmaxf(m, __shfl_xor_sync(~0u, m, s));
    if (lane == 0) red[wid] = m;
    __syncthreads();
    m = red[lane & 7];
    #pragma unroll
    for (int s = 4; s > 0; s >>= 1) m = fmaxf(m, __shfl_xor_sync(~0u, m, s));

    float sum = 0.f;
    for (int k = tid; k < L; k += 256) {
        float e = __expf(ebuf[k] - m);
        ebuf[k] = e;
        sum += e;
    }
    #pragma unroll
    for (int s = 16; s > 0; s >>= 1) sum += __shfl_xor_sync(~0u, sum, s);
    __syncthreads();
    if (lane == 0) red[wid] = sum;
    __syncthreads();
    sum = red[lane & 7];
    #pragma unroll
    for (int s = 4; s > 0; s >>= 1) sum += __shfl_xor_sync(~0u, sum, s);

    const float inv = 1.0f / sum;
    for (int k = tid; k < L; k += 256) pa[k] = __float2half_rn(ebuf[k] * inv);
    for (int k = L + tid; k < kend; k += 256) pa[k] = __half(0.f);
}

// ---------------------------------------------------------------------------
// 4) out = attn @ V  (B = V^T n-major; k truncated at causal boundary)
// ---------------------------------------------------------------------------
__global__ __launch_bounds__(256, 2)
void attnv_kernel()
{
    extern __shared__ uint32_t sm[];
    uint32_t* Ab = sm;
    uint32_t* Bb = Ab + 2 * BM * HST;
    const int tid = threadIdx.x;
    const int lane = tid & 31, wid = tid >> 5;
    const int wm = (wid & 3) * 32, wn = (wid >> 2) * 64;
    ACC_INIT();
    LDSM_OFFSETS();
    const uint32_t sA = (uint32_t)__cvta_generic_to_shared(Ab) + aoff;
    const uint32_t sB = (uint32_t)__cvta_generic_to_shared(Bb) + boff;
    const int b  = blockIdx.z;
    const int q0 = blockIdx.y * BM;
    const int n0 = blockIdx.x * BN;
    const __half* A  = g_attn + (size_t)(b * SEQ) * SEQ;
    const __half* VT = g_vT + ((size_t)b * DIM + n0) * SEQ;

    STAGE_H(Ab, 256, 128, A + (size_t)(q0 + r) * SEQ + hh);
    STAGE_H(Bb, 256, 128, VT + (size_t)r * SEQ + hh);
    CP_COMMIT();

    const int NC = (q0 + BM) / BK;
    for (int c = 0; c < NC; c++) {
        const int bf = c & 1;
        CP_WAIT0();
        __syncthreads();
        if (c + 1 < NC) {
            const int k1 = (c + 1) * BK;
            uint32_t* An = Ab + (bf ^ 1) * BM * HST;
            uint32_t* Bn = Bb + (bf ^ 1) * BM * HST;
            STAGE_H(An, 256, 128, A + (size_t)(q0 + r) * SEQ + k1 + hh);
            STAGE_H(Bn, 256, 128, VT + (size_t)r * SEQ + k1 + hh);
            CP_COMMIT();
        }
        TILE_LDSM(sA + bf * (BM * HST * 4), sB + bf * (BM * HST * 4));
    }
    const int g = lane >> 2, t = lane & 3;
    #pragma unroll
    for (int mi = 0; mi < 2; mi++)
        #pragma unroll
        for (int ni = 0; ni < 8; ni++) {
            int r0 = q0 + wm + mi * 16 + g;
            int c  = n0 + wn + ni * 8 + t * 2;
            __half* base = g_attn_out + (size_t)(b * SEQ) * DIM;
            *(__half2*)(base + (size_t)r0 * DIM + c) =
                __floats2half2_rn(acc[mi][ni][0], acc[mi][ni][1]);
            *(__half2*)(base + (size_t)(r0 + 8) * DIM + c) =
                __floats2half2_rn(acc[mi][ni][2], acc[mi][ni][3]);
        }
}

// ---------------------------------------------------------------------------
// 5) logits = attn_out @ fc_w^T + fc_b  — 3-stage cp.async ring (wait_group 1)
// ---------------------------------------------------------------------------
#define LBM 256
__global__ __launch_bounds__(512, 1)
void logits_kernel(const float* __restrict__ bias, float* __restrict__ out)
{
    extern __shared__ uint32_t sm[];
    uint32_t* Ab = sm;                         // 3 * LBM*HST
    uint32_t* Bb = Ab + 3 * LBM * HST;         // 3 * BM*HST
    const int tid = threadIdx.x;
    const int lane = tid & 31, wid = tid >> 5;
    const int wm = (wid & 7) * 32, wn = (wid >> 3) * 64;
    ACC_INIT();
    LDSM_OFFSETS();
    const uint32_t sA = (uint32_t)__cvta_generic_to_shared(Ab) + aoff;
    const uint32_t sB = (uint32_t)__cvta_generic_to_shared(Bb) + boff;
    const int m0 = blockIdx.y * LBM;
    const int n0 = blockIdx.x * BN;

    #pragma unroll
    for (int p = 0; p < 2; p++) {
        STAGE_H(Ab + p * LBM * HST, 512, 256,
                g_attn_out + (size_t)(m0 + r) * DIM + p * BK + hh);
        STAGE_H(Bb + p * BM * HST, 512, 128,
                g_fcwT + (size_t)(n0 + r) * DIM + p * BK + hh);
        CP_COMMIT();
    }

    for (int c = 0; c < 8; c++) {
        const int cur = c % 3;
        if (c + 1 < 8) CP_WAIT1(); else CP_WAIT0();
        __syncthreads();
        if (c + 2 < 8) {
            const int nxt = (c + 2) % 3;
            const int k1 = (c + 2) * BK;
            STAGE_H(Ab + nxt * LBM * HST, 512, 256,
                    g_attn_out + (size_t)(m0 + r) * DIM + k1 + hh);
            STAGE_H(Bb + nxt * BM * HST, 512, 128,
                    g_fcwT + (size_t)(n0 + r) * DIM + k1 + hh);
            CP_COMMIT();
        }
        TILE_LDSM(sA + cur * (LBM * HST * 4), sB + cur * (BM * HST * 4));
    }
    const int g = lane >> 2, t = lane & 3;
    #pragma unroll
    for (int mi = 0; mi < 2; mi++)
        #pragma unroll
        for (int ni = 0; ni < 8; ni++) {
            int r0 = m0 + wm + mi * 16 + g;
            int c  = n0 + wn + ni * 8 + t * 2;
            float b0 = bias[c], b1 = bias[c + 1];
            float* p0 = out + (size_t)r0 * VOCAB + c;
            float* p1 = out + (size_t)(r0 + 8) * VOCAB + c;
            *(float2*)p0 = make_float2(acc[mi][ni][0] + b0, acc[mi][ni][1] + b1);
            *(float2*)p1 = make_float2(acc[mi][ni][2] + b0, acc[mi][ni][3] + b1);
        }
}

// ---------------------------------------------------------------------------
extern "C" void kernel_launch(void* const* d_in, const int* in_sizes, int n_in,
                              void* d_out, int out_size)
{
    (void)in_sizes; (void)n_in; (void)out_size;
    const int*   x     = (const int*)  d_in[0];
    const float* embed = (const float*)d_in[1];
    const float* qkv_w = (const float*)d_in[2];
    const float* qkv_b = (const float*)d_in[3];
    const float* fc_w  = (const float*)d_in[4];
    const float* fc_b  = (const float*)d_in[5];
    float* out = (float*)d_out;

    const int smem_qkv    = (128 + 4 * BM * HST) * 4;            // ~74.2 KB
    const int smem_scores = (4 * BM * HST) * 4;                  // ~73.7 KB
    const int smem_attnv  = (4 * BM * HST) * 4;                  // ~73.7 KB
    const int smem_logits = (3 * LBM * HST + 3 * BM * HST) * 4;  // ~165.9 KB

    cudaFuncSetAttribute(qkv_kernel,
        cudaFuncAttributeMaxDynamicSharedMemorySize, smem_qkv);
    cudaFuncSetAttribute(scores_kernel,
        cudaFuncAttributeMaxDynamicSharedMemorySize, smem_scores);
    cudaFuncSetAttribute(attnv_kernel,
        cudaFuncAttributeMaxDynamicSharedMemorySize, smem_attnv);
    cudaFuncSetAttribute(logits_kernel,
        cudaFuncAttributeMaxDynamicSharedMemorySize, smem_logits);

    __half* emb_dst;  cudaGetSymbolAddress((void**)&emb_dst,  g_embed_h);
    __half* qkvw_dst; cudaGetSymbolAddress((void**)&qkvw_dst, g_qkvwT);
    __half* fcw_dst;  cudaGetSymbolAddress((void**)&fcw_dst,  g_fcwT);

    cvt_half_kernel<<<VOCAB * DIM / 4 / 256, 256>>>(embed, emb_dst,
                                                    VOCAB * DIM / 4);
    transpose_cvt_kernel<<<dim3(NQKV / 32, DIM / 32), 256>>>(qkv_w, qkvw_dst, NQKV);
    transpose_cvt_kernel<<<dim3(VOCAB / 32, DIM / 32), 256>>>(fc_w, fcw_dst, VOCAB);

    qkv_kernel    <<<dim3(NQKV / BN, MTOK / BM), 256, smem_qkv>>>(x, qkv_b);
    scores_kernel <<<dim3(SEQ / BN, SEQ / BM, BATCH), 256, smem_scores>>>();
    softmax_kernel<<<MTOK, 256>>>();
    attnv_kernel  <<<dim3(DIM / BN, SEQ / BM, BATCH), 256, smem_attnv>>>();
    logits_kernel <<<dim3(VOCAB / BN, MTOK / LBM), 512, smem_logits>>>(fc_b, out);
}